// round 1
// baseline (speedup 1.0000x reference)
#include <cuda_runtime.h>

#define Bn 2
#define Nn 2048
#define Kn 256
#define Dn 768
#define Hn 256
#define Ln 64
#define BND (Bn*Nn*Dn)
#define BKD (Bn*Kn*Dn)
#define BKH (Bn*Kn*Hn)

// ---------------- scratch (device globals; no allocations allowed) ----------
__device__ float g_left [BKH];
__device__ float g_right[BKH];
__device__ float g_outwT[Hn*Ln];      // [h][l]
__device__ float g_AwT  [Ln*Dn];      // [l][d]
__device__ float g_BwT  [Ln*Dn];      // [l][d]
__device__ float g_part [4][BKD];     // (mode,split) partial contexts
__device__ float g_c    [BKD];
__device__ float g_gate [BKD];

__device__ __forceinline__ float sigmoidf(float x) {
    return 1.0f / (1.0f + __expf(-x));
}

// 64x64 block-tile GEMM inner product step over a TK=16 chunk.
// As[k][m], Bs[k][n]; thread computes a 4x4 micro-tile.
__device__ __forceinline__ void mm_core(const float As[16][68], const float Bs[16][68],
                                        int tm, int tn, float acc[4][4]) {
#pragma unroll
    for (int kk = 0; kk < 16; kk++) {
        float4 a4 = *(const float4*)&As[kk][tm];
        float4 b4 = *(const float4*)&Bs[kk][tn];
        float a[4] = {a4.x, a4.y, a4.z, a4.w};
        float b[4] = {b4.x, b4.y, b4.z, b4.w};
#pragma unroll
        for (int i2 = 0; i2 < 4; i2++)
#pragma unroll
            for (int j2 = 0; j2 < 4; j2++)
                acc[i2][j2] += a[i2] * b[j2];
    }
}

// ---------------- prep: weight transposes --------------------------------
__global__ void prep_kernel(const float* __restrict__ out_w,
                            const float* __restrict__ A_w,
                            const float* __restrict__ B_w) {
    int i = blockIdx.x * blockDim.x + threadIdx.x;
    if (i < Hn * Ln) { int h = i / Ln, l = i - h * Ln; g_outwT[i] = out_w[l * Hn + h]; }
    if (i < Ln * Dn) { int l = i / Dn, d = i - l * Dn; g_AwT[i] = A_w[d * Ln + l];
                                                      g_BwT[i] = B_w[d * Ln + l]; }
}

// ---------------- init copies ---------------------------------------------
__global__ void copy_init_kernel(const float* __restrict__ all_vecs,
                                 const float* __restrict__ span_vecs,
                                 float* __restrict__ outAll,
                                 float* __restrict__ outU) {
    int i = blockIdx.x * blockDim.x + threadIdx.x;
    if (i < BND) outAll[i] = all_vecs[i];
    if (i < BKD) outU[i]   = span_vecs[i];
}

// ---------------- left/right projections: [512 x 512] = u @ [left_w|right_w]^T
__global__ __launch_bounds__(256) void proj_kernel(const float* __restrict__ u,
        const float* __restrict__ left_w,  const float* __restrict__ left_b,
        const float* __restrict__ right_w, const float* __restrict__ right_b) {
    __shared__ float As[16][68];
    __shared__ float Bs[16][68];
    const int tid = threadIdx.x;
    const int m0 = blockIdx.x * 64, n0 = blockIdx.y * 64;
    const int tm = (tid / 16) * 4, tn = (tid % 16) * 4;
    const int lr = tid / 4, lc4 = (tid % 4) * 4;
    float acc[4][4] = {};
    const int nrow = n0 + lr;
    const float* W = (nrow < Hn) ? left_w : right_w;
    const int wrow = (nrow < Hn) ? nrow : nrow - Hn;
    for (int kb = 0; kb < Dn; kb += 16) {
        float4 av = *(const float4*)&u[(m0 + lr) * Dn + kb + lc4];
        As[lc4 + 0][lr] = av.x; As[lc4 + 1][lr] = av.y;
        As[lc4 + 2][lr] = av.z; As[lc4 + 3][lr] = av.w;
        float4 bv = *(const float4*)&W[wrow * Dn + kb + lc4];
        Bs[lc4 + 0][lr] = bv.x; Bs[lc4 + 1][lr] = bv.y;
        Bs[lc4 + 2][lr] = bv.z; Bs[lc4 + 3][lr] = bv.w;
        __syncthreads();
        mm_core(As, Bs, tm, tn, acc);
        __syncthreads();
    }
#pragma unroll
    for (int i2 = 0; i2 < 4; i2++)
#pragma unroll
        for (int j2 = 0; j2 < 4; j2++) {
            int m = m0 + tm + i2, n = n0 + tn + j2;
            if (n < Hn) g_left [m * Hn + n]      = acc[i2][j2] + left_b[n];
            else        g_right[m * Hn + n - Hn] = acc[i2][j2] + right_b[n - Hn];
        }
}

// ---------------- fused pair-scorer ---------------------------------------
// scores[b,i,j,l] = sum_h relu(left[b,i,h]+right[b,j,h]+dist_emb[bkt(i,j),h]) * out_w[l,h] + out_b[l]
// block: (j-tile of 64, i, b); M=j(64), N=l(64), K=h(256)
__global__ __launch_bounds__(256) void scores_kernel(
        const int* __restrict__ span_begin, const int* __restrict__ span_end,
        const float* __restrict__ dist_emb, const float* __restrict__ out_b,
        float* __restrict__ scores) {
    __shared__ float As[16][68];   // [h][j]
    __shared__ float Bs[16][68];   // [h][l]
    __shared__ float leftS[Hn];
    __shared__ int   bkt[64];
    const int tid = threadIdx.x;
    const int b = blockIdx.z, i = blockIdx.y, j0 = blockIdx.x * 64;
    if (tid < 64) {
        int dd = span_begin[b * Kn + j0 + tid] - span_end[b * Kn + i];
        int ad = abs(dd);
        bkt[tid] = ad > 63 ? 63 : ad;
    }
    for (int h = tid; h < Hn; h += 256) leftS[h] = g_left[(b * Kn + i) * Hn + h];
    __syncthreads();
    const int tm = (tid / 16) * 4, tn = (tid % 16) * 4;
    const int lr = tid / 4, lc4 = (tid % 4) * 4;
    float acc[4][4] = {};
    for (int hb = 0; hb < Hn; hb += 16) {
        int jj = j0 + lr;
        float4 rv = *(const float4*)&g_right[(b * Kn + jj) * Hn + hb + lc4];
        float4 dv = *(const float4*)&dist_emb[bkt[lr] * Hn + hb + lc4];
        float4 lv = *(const float4*)&leftS[hb + lc4];
        As[lc4 + 0][lr] = fmaxf(lv.x + rv.x + dv.x, 0.f);
        As[lc4 + 1][lr] = fmaxf(lv.y + rv.y + dv.y, 0.f);
        As[lc4 + 2][lr] = fmaxf(lv.z + rv.z + dv.z, 0.f);
        As[lc4 + 3][lr] = fmaxf(lv.w + rv.w + dv.w, 0.f);
        *(float4*)&Bs[tid / 16][(tid % 16) * 4] =
            *(const float4*)&g_outwT[(hb + tid / 16) * Ln + (tid % 16) * 4];
        __syncthreads();
        mm_core(As, Bs, tm, tn, acc);
        __syncthreads();
    }
#pragma unroll
    for (int i2 = 0; i2 < 4; i2++)
#pragma unroll
        for (int j2 = 0; j2 < 4; j2++) {
            int j = j0 + tm + i2, l = tn + j2;
            scores[((size_t)(b * Kn + i) * Kn + j) * Ln + l] = acc[i2][j2] + out_b[l];
        }
}

// ---------------- context GEMMs -------------------------------------------
// mode 0: ctxt1[b,j,d] = sum_{r=(i,l)} sig(scores[b,i,j,l])*mask[b,i,j] * (u[b,i,d]*AwT[l,d])
// mode 1: ctxt2[b,i,d] = sum_{r=(j,l)} sig(scores[b,i,j,l])*mask[b,i,j] * (u[b,j,d]*BwT[l,d])
// grid: x = m-tile(4), y = d-tile(12), z = b*4 + mode*2 + split
__global__ __launch_bounds__(256) void ctxt_kernel(const float* __restrict__ scores,
                                                   const float* __restrict__ u,
                                                   const float* __restrict__ mask) {
    __shared__ float As[16][68];  // [r][m]
    __shared__ float Bs[16][68];  // [r][d]
    const int tid = threadIdx.x;
    const int z = blockIdx.z;
    const int b = z >> 2, mode = (z >> 1) & 1, split = z & 1;
    const int m0 = blockIdx.x * 64, d0 = blockIdx.y * 64;
    const float* wT = (mode == 0) ? g_AwT : g_BwT;
    const float* scoresB = scores + (size_t)b * Kn * Kn * Ln;
    const float* maskB   = mask   + (size_t)b * Kn * Kn;
    const float* uB      = u      + (size_t)b * Kn * Dn;
    const int tm = (tid / 16) * 4, tn = (tid % 16) * 4;
    const int lr = tid / 4, lc4 = (tid % 4) * 4;
    const int brl = tid / 16, bd4 = (tid % 16) * 4;
    float acc[4][4] = {};
    const int rBeg = split * 8192, rEnd = rBeg + 8192;
    for (int rb = rBeg; rb < rEnd; rb += 16) {
        const int other = rb >> 6;      // i (mode0) / j (mode1), constant over chunk
        const int l0 = rb & 63;
        float4 s4; float mk;
        if (mode == 0) {
            s4 = *(const float4*)&scoresB[((size_t)other * Kn + m0 + lr) * Ln + l0 + lc4];
            mk = maskB[other * Kn + m0 + lr];
        } else {
            s4 = *(const float4*)&scoresB[(size_t)(m0 + lr) * (Kn * Ln) + rb + lc4];
            mk = maskB[(m0 + lr) * Kn + other];
        }
        As[lc4 + 0][lr] = mk * sigmoidf(s4.x);
        As[lc4 + 1][lr] = mk * sigmoidf(s4.y);
        As[lc4 + 2][lr] = mk * sigmoidf(s4.z);
        As[lc4 + 3][lr] = mk * sigmoidf(s4.w);
        {
            float4 uv = *(const float4*)&uB[other * Dn + d0 + bd4];
            float4 wv = *(const float4*)&wT[(l0 + brl) * Dn + d0 + bd4];
            float4 bb = make_float4(uv.x * wv.x, uv.y * wv.y, uv.z * wv.z, uv.w * wv.w);
            *(float4*)&Bs[brl][bd4] = bb;
        }
        __syncthreads();
        mm_core(As, Bs, tm, tn, acc);
        __syncthreads();
    }
    float* dst = g_part[mode * 2 + split];
#pragma unroll
    for (int i2 = 0; i2 < 4; i2++)
#pragma unroll
        for (int j2 = 0; j2 < 4; j2++)
            dst[((size_t)b * Kn + m0 + tm + i2) * Dn + d0 + tn + j2] = acc[i2][j2];
}

__global__ void combine_kernel(const float* __restrict__ slen) {
    int i = blockIdx.x * blockDim.x + threadIdx.x;
    if (i < BKD) {
        int b = i / (Kn * Dn);
        g_c[i] = (g_part[0][i] + g_part[1][i] + g_part[2][i] + g_part[3][i]) * (1.0f / slen[b]);
    }
}

// ---------------- gate GEMM: g = sigmoid([u|c] @ gate_w^T + gate_b) --------
__global__ __launch_bounds__(256) void gate_kernel(const float* __restrict__ u,
        const float* __restrict__ gate_w, const float* __restrict__ gate_b) {
    __shared__ float As[16][68];
    __shared__ float Bs[16][68];
    const int tid = threadIdx.x;
    const int m0 = blockIdx.x * 64, n0 = blockIdx.y * 64;
    const int tm = (tid / 16) * 4, tn = (tid % 16) * 4;
    const int lr = tid / 4, lc4 = (tid % 4) * 4;
    float acc[4][4] = {};
    for (int kb = 0; kb < 2 * Dn; kb += 16) {
        const float* Aptr = (kb < Dn) ? &u[(m0 + lr) * Dn + kb + lc4]
                                      : &g_c[(m0 + lr) * Dn + (kb - Dn) + lc4];
        float4 av = *(const float4*)Aptr;
        As[lc4 + 0][lr] = av.x; As[lc4 + 1][lr] = av.y;
        As[lc4 + 2][lr] = av.z; As[lc4 + 3][lr] = av.w;
        float4 bv = *(const float4*)&gate_w[(size_t)(n0 + lr) * (2 * Dn) + kb + lc4];
        Bs[lc4 + 0][lr] = bv.x; Bs[lc4 + 1][lr] = bv.y;
        Bs[lc4 + 2][lr] = bv.z; Bs[lc4 + 3][lr] = bv.w;
        __syncthreads();
        mm_core(As, Bs, tm, tn, acc);
        __syncthreads();
    }
#pragma unroll
    for (int i2 = 0; i2 < 4; i2++)
#pragma unroll
        for (int j2 = 0; j2 < 4; j2++) {
            int n = n0 + tn + j2;
            g_gate[(size_t)(m0 + tm + i2) * Dn + n] = sigmoidf(acc[i2][j2] + gate_b[n]);
        }
}

__global__ void update_kernel(float* __restrict__ u) {
    int i = blockIdx.x * blockDim.x + threadIdx.x;
    if (i < BKD) {
        float g = g_gate[i];
        u[i] = g * u[i] + (1.0f - g) * g_c[i];
    }
}

// ---------------- final scatter -------------------------------------------
__global__ void scatter_kernel(const int* __restrict__ prune, const float* __restrict__ slen,
                               const float* __restrict__ u, float* __restrict__ outAll) {
    int i = blockIdx.x * blockDim.x + threadIdx.x;
    if (i < BKD) {
        int d = i % Dn, bk = i / Dn, b = bk / Kn, k = bk % Kn;
        if ((float)k < slen[b]) {
            int row = prune[bk];
            outAll[((size_t)b * Nn + row) * Dn + d] = u[i];
        }
    }
}

// ---------------- driver ---------------------------------------------------
extern "C" void kernel_launch(void* const* d_in, const int* in_sizes, int n_in,
                              void* d_out, int out_size) {
    (void)in_sizes; (void)n_in; (void)out_size;
    const float* all_vecs  = (const float*)d_in[0];
    const float* span_vecs = (const float*)d_in[1];
    const int*   span_beg  = (const int*)  d_in[2];
    const int*   span_end  = (const int*)  d_in[3];
    const float* mask      = (const float*)d_in[4];
    const float* slen      = (const float*)d_in[5];
    const int*   prune     = (const int*)  d_in[6];
    const float* left_w    = (const float*)d_in[7];
    const float* left_b    = (const float*)d_in[8];
    const float* right_w   = (const float*)d_in[9];
    const float* right_b   = (const float*)d_in[10];
    const float* dist_emb  = (const float*)d_in[11];
    const float* out_w     = (const float*)d_in[12];
    const float* out_b     = (const float*)d_in[13];
    const float* A_w       = (const float*)d_in[14];
    const float* B_w       = (const float*)d_in[15];
    const float* gate_w    = (const float*)d_in[16];
    const float* gate_b    = (const float*)d_in[17];

    float* outAll = (float*)d_out;           // [B,N,D]
    float* outU   = outAll + BND;            // [B,K,D]  (working "update" buffer)
    float* outS   = outU + BKD;              // [B,K,K,L] (working "scores" buffer)

    prep_kernel<<<(Ln * Dn + 255) / 256, 256>>>(out_w, A_w, B_w);
    copy_init_kernel<<<(BND + 255) / 256, 256>>>(all_vecs, span_vecs, outAll, outU);

    proj_kernel<<<dim3(8, 8), 256>>>(outU, left_w, left_b, right_w, right_b);
    scores_kernel<<<dim3(4, Kn, Bn), 256>>>(span_beg, span_end, dist_emb, out_b, outS);

    for (int t = 0; t < 3; t++) {
        ctxt_kernel<<<dim3(4, 12, 8), 256>>>(outS, outU, mask);
        combine_kernel<<<(BKD + 255) / 256, 256>>>(slen);
        gate_kernel<<<dim3(8, 12), 256>>>(outU, gate_w, gate_b);
        update_kernel<<<(BKD + 255) / 256, 256>>>(outU);
        proj_kernel<<<dim3(8, 8), 256>>>(outU, left_w, left_b, right_w, right_b);
        scores_kernel<<<dim3(4, Kn, Bn), 256>>>(span_beg, span_end, dist_emb, out_b, outS);
    }

    scatter_kernel<<<(BKD + 255) / 256, 256>>>(prune, slen, outU, outAll);
}

// round 2
// speedup vs baseline: 1.7871x; 1.7871x over previous
#include <cuda_runtime.h>
#include <cstdint>

#define Bn 2
#define Nn 2048
#define Kn 256
#define Dn 768
#define Hn 256
#define Ln 64
#define BND (Bn*Nn*Dn)
#define BKD (Bn*Kn*Dn)
#define BKH (Bn*Kn*Hn)
#define BKKL ((size_t)Bn*Kn*Kn*Ln)

// ---------------- scratch (device globals; no allocations allowed) ----------
__device__ float g_left [BKH];
__device__ float g_right[BKH];
__device__ float g_outwT[Hn*Ln];      // [h][l], tf32-rounded
__device__ float g_AwT  [Ln*Dn];      // [l][d], tf32-rounded
__device__ float g_BwT  [Ln*Dn];      // [l][d], tf32-rounded
__device__ float g_probs[BKKL];       // sigmoid(score)*mask, tf32-rounded
__device__ float g_part [8][BKD];     // (mode*4+split) partial contexts
__device__ float g_c    [BKD];
__device__ float g_gate [BKD];

__device__ __forceinline__ float sigmoidf(float x) {
    return 1.0f / (1.0f + __expf(-x));
}
__device__ __forceinline__ uint32_t tf32r(float x) {
    uint32_t u; asm("cvt.rna.tf32.f32 %0, %1;" : "=r"(u) : "f"(x)); return u;
}
__device__ __forceinline__ float tf32rf(float x) {
    return __uint_as_float(tf32r(x));
}
__device__ __forceinline__ void mma8(float c[4], uint32_t a0, uint32_t a1, uint32_t a2,
                                     uint32_t a3, uint32_t b0, uint32_t b1) {
    asm("mma.sync.aligned.m16n8k8.row.col.f32.tf32.tf32.f32 "
        "{%0,%1,%2,%3},{%4,%5,%6,%7},{%8,%9},{%0,%1,%2,%3};"
        : "+f"(c[0]), "+f"(c[1]), "+f"(c[2]), "+f"(c[3])
        : "r"(a0), "r"(a1), "r"(a2), "r"(a3), "r"(b0), "r"(b1));
}

// Block template: 256 threads = 8 warps (4 m-groups x 2 n-groups).
// Tile M=128, N=64, BK=32. Warp tile 32m x 32n via m16n8k8.
// As[m][k] layout, 36-float rows: fragment LDS is conflict-free.

// ---------------- prep: tf32-rounded weight transposes ---------------------
__global__ void prep_kernel(const float* __restrict__ out_w,
                            const float* __restrict__ A_w,
                            const float* __restrict__ B_w) {
    int i = blockIdx.x * blockDim.x + threadIdx.x;
    if (i < Hn * Ln) { int h = i / Ln, l = i - h * Ln; g_outwT[i] = tf32rf(out_w[l * Hn + h]); }
    if (i < Ln * Dn) { int l = i / Dn, d = i - l * Dn; g_AwT[i] = tf32rf(A_w[d * Ln + l]);
                                                      g_BwT[i] = tf32rf(B_w[d * Ln + l]); }
}

__global__ void copy_init_kernel(const float* __restrict__ all_vecs,
                                 const float* __restrict__ span_vecs,
                                 float* __restrict__ outAll,
                                 float* __restrict__ outU) {
    int i = blockIdx.x * blockDim.x + threadIdx.x;
    if (i < BND) outAll[i] = all_vecs[i];
    if (i < BKD) outU[i]   = span_vecs[i];
}

// ---------------- proj: [512 x 512] = u @ [left_w | right_w]^T -------------
__global__ __launch_bounds__(256) void proj_kernel(const float* __restrict__ u,
        const float* __restrict__ left_w,  const float* __restrict__ left_b,
        const float* __restrict__ right_w, const float* __restrict__ right_b) {
    __shared__ float As[128][36];
    const int tid = threadIdx.x;
    const int warp = tid >> 5, lane = tid & 31;
    const int wm = warp & 3, wn = warp >> 2;
    const int grp = lane >> 2, q = lane & 3;
    const int m0 = blockIdx.x * 128, n0 = blockIdx.y * 64;
    const bool isL = (n0 < Hn);
    const float* W    = isL ? left_w : right_w;
    const float* bias = isL ? left_b : right_b;
    float* OUT        = isL ? g_left : g_right;
    const int nloc0 = isL ? n0 : n0 - Hn;
    const int fm = tid >> 1, fh = tid & 1;
    float acc[2][4][4] = {};

    for (int kb = 0; kb < Dn; kb += 32) {
        const float* src = u + (size_t)(m0 + fm) * Dn + kb + fh * 16;
#pragma unroll
        for (int e = 0; e < 4; e++) {
            float4 v = *(const float4*)(src + 4 * e);
            int c = fh * 16 + 4 * e;
            As[fm][c + 0] = tf32rf(v.x); As[fm][c + 1] = tf32rf(v.y);
            As[fm][c + 2] = tf32rf(v.z); As[fm][c + 3] = tf32rf(v.w);
        }
        __syncthreads();
#pragma unroll
        for (int k0 = 0; k0 < 32; k0 += 8) {
            uint32_t b0[4], b1[4];
#pragma unroll
            for (int ni = 0; ni < 4; ni++) {
                int n = nloc0 + wn * 32 + ni * 8 + grp;
                b0[ni] = tf32r(W[(size_t)n * Dn + kb + k0 + q]);
                b1[ni] = tf32r(W[(size_t)n * Dn + kb + k0 + q + 4]);
            }
#pragma unroll
            for (int mi = 0; mi < 2; mi++) {
                int mb = wm * 32 + mi * 16;
                uint32_t a0 = __float_as_uint(As[mb + grp][k0 + q]);
                uint32_t a1 = __float_as_uint(As[mb + 8 + grp][k0 + q]);
                uint32_t a2 = __float_as_uint(As[mb + grp][k0 + q + 4]);
                uint32_t a3 = __float_as_uint(As[mb + 8 + grp][k0 + q + 4]);
#pragma unroll
                for (int ni = 0; ni < 4; ni++)
                    mma8(acc[mi][ni], a0, a1, a2, a3, b0[ni], b1[ni]);
            }
        }
        __syncthreads();
    }
#pragma unroll
    for (int mi = 0; mi < 2; mi++) {
        int r0 = m0 + wm * 32 + mi * 16 + grp;
#pragma unroll
        for (int ni = 0; ni < 4; ni++) {
            int c = nloc0 + wn * 32 + ni * 8 + 2 * q;
            OUT[(size_t)r0 * Hn + c]       = acc[mi][ni][0] + bias[c];
            OUT[(size_t)r0 * Hn + c + 1]   = acc[mi][ni][1] + bias[c + 1];
            OUT[(size_t)(r0 + 8) * Hn + c]     = acc[mi][ni][2] + bias[c];
            OUT[(size_t)(r0 + 8) * Hn + c + 1] = acc[mi][ni][3] + bias[c + 1];
        }
    }
}

// ---------------- fused pair-scorer + probs -------------------------------
// scores[b,i,j,l]; probs[b,i,j,l] = sigmoid(score)*mask (tf32-rounded)
// grid: (j-tile of 128, i, b). M=j(128), N=l(64), K=h(256)
__global__ __launch_bounds__(256) void scores_kernel(
        const int* __restrict__ span_begin, const int* __restrict__ span_end,
        const float* __restrict__ dist_emb, const float* __restrict__ out_b,
        const float* __restrict__ mask, float* __restrict__ scores) {
    __shared__ float As[128][36];
    __shared__ float leftS[Hn];
    const int tid = threadIdx.x;
    const int warp = tid >> 5, lane = tid & 31;
    const int wm = warp & 3, wn = warp >> 2;
    const int grp = lane >> 2, q = lane & 3;
    const int b = blockIdx.z, i = blockIdx.y, j0 = blockIdx.x * 128;
    const int fm = tid >> 1, fh = tid & 1;

    leftS[tid] = g_left[(size_t)(b * Kn + i) * Hn + tid];
    int dd = span_begin[b * Kn + j0 + fm] - span_end[b * Kn + i];
    int ad = abs(dd); const int bkt = ad > 63 ? 63 : ad;
    __syncthreads();

    float acc[2][4][4] = {};
    for (int hb = 0; hb < Hn; hb += 32) {
        const float* rsrc = g_right + (size_t)(b * Kn + j0 + fm) * Hn + hb + fh * 16;
        const float* dsrc = dist_emb + (size_t)bkt * Hn + hb + fh * 16;
#pragma unroll
        for (int e = 0; e < 4; e++) {
            float4 rv = *(const float4*)(rsrc + 4 * e);
            float4 dv = *(const float4*)(dsrc + 4 * e);
            int c = fh * 16 + 4 * e;
            float4 lv = *(const float4*)(&leftS[hb + c]);
            As[fm][c + 0] = tf32rf(fmaxf(lv.x + rv.x + dv.x, 0.f));
            As[fm][c + 1] = tf32rf(fmaxf(lv.y + rv.y + dv.y, 0.f));
            As[fm][c + 2] = tf32rf(fmaxf(lv.z + rv.z + dv.z, 0.f));
            As[fm][c + 3] = tf32rf(fmaxf(lv.w + rv.w + dv.w, 0.f));
        }
        __syncthreads();
#pragma unroll
        for (int k0 = 0; k0 < 32; k0 += 8) {
            uint32_t b0[4], b1[4];
#pragma unroll
            for (int ni = 0; ni < 4; ni++) {
                int n = wn * 32 + ni * 8 + grp;
                b0[ni] = __float_as_uint(g_outwT[(size_t)(hb + k0 + q) * Ln + n]);
                b1[ni] = __float_as_uint(g_outwT[(size_t)(hb + k0 + q + 4) * Ln + n]);
            }
#pragma unroll
            for (int mi = 0; mi < 2; mi++) {
                int mb = wm * 32 + mi * 16;
                uint32_t a0 = __float_as_uint(As[mb + grp][k0 + q]);
                uint32_t a1 = __float_as_uint(As[mb + 8 + grp][k0 + q]);
                uint32_t a2 = __float_as_uint(As[mb + grp][k0 + q + 4]);
                uint32_t a3 = __float_as_uint(As[mb + 8 + grp][k0 + q + 4]);
#pragma unroll
                for (int ni = 0; ni < 4; ni++)
                    mma8(acc[mi][ni], a0, a1, a2, a3, b0[ni], b1[ni]);
            }
        }
        __syncthreads();
    }
    float* scRow = scores + (size_t)(b * Kn + i) * (Kn * Ln);
    float* prRow = g_probs + (size_t)(b * Kn + i) * (Kn * Ln);
    const float* mkRow = mask + (size_t)(b * Kn + i) * Kn;
#pragma unroll
    for (int mi = 0; mi < 2; mi++) {
        int j0l = wm * 32 + mi * 16 + grp;
        float mk0 = mkRow[j0 + j0l], mk1 = mkRow[j0 + j0l + 8];
#pragma unroll
        for (int ni = 0; ni < 4; ni++) {
            int c = wn * 32 + ni * 8 + 2 * q;
#pragma unroll
            for (int e = 0; e < 2; e++) {
                float s0 = acc[mi][ni][e]     + out_b[c + e];
                float s1 = acc[mi][ni][2 + e] + out_b[c + e];
                scRow[(size_t)(j0 + j0l) * Ln + c + e]     = s0;
                scRow[(size_t)(j0 + j0l + 8) * Ln + c + e] = s1;
                prRow[(size_t)(j0 + j0l) * Ln + c + e]     = tf32rf(sigmoidf(s0) * mk0);
                prRow[(size_t)(j0 + j0l + 8) * Ln + c + e] = tf32rf(sigmoidf(s1) * mk1);
            }
        }
    }
}

// ---------------- context GEMMs -------------------------------------------
// mode 0: ctxt1[b,j,d] += probs[b,i,j,l] * u[b,i,d] * AwT[l,d]   (r=(i,l))
// mode 1: ctxt2[b,i,d] += probs[b,i,j,l] * u[b,j,d] * BwT[l,d]   (r=(j,l))
// grid: x=m-tile(2), y=d-tile(12), z = b*8 + mode*4 + split
__global__ __launch_bounds__(256) void ctxt_kernel(const float* __restrict__ u) {
    __shared__ float As[128][36];
    const int tid = threadIdx.x;
    const int warp = tid >> 5, lane = tid & 31;
    const int wm = warp & 3, wn = warp >> 2;
    const int grp = lane >> 2, q = lane & 3;
    const int z = blockIdx.z;
    const int b = z >> 3, mode = (z >> 2) & 1, split = z & 3;
    const int m0 = blockIdx.x * 128, d0 = blockIdx.y * 64;
    const float* wT = (mode == 0) ? g_AwT : g_BwT;
    const float* probsB = g_probs + (size_t)b * Kn * Kn * Ln;
    const float* uB     = u       + (size_t)b * Kn * Dn;
    const int fm = tid >> 1, fh = tid & 1;
    int dcol[4];
#pragma unroll
    for (int ni = 0; ni < 4; ni++) dcol[ni] = d0 + wn * 32 + ni * 8 + grp;

    float acc[2][4][4] = {};
    const int rBeg = split * 4096, rEnd = rBeg + 4096;
    for (int rb = rBeg; rb < rEnd; rb += 32) {
        const int other = rb >> 6;
        const int l0 = rb & 63;
        const float* src = (mode == 0)
            ? probsB + ((size_t)other * Kn + m0 + fm) * Ln + l0 + fh * 16
            : probsB + ((size_t)(m0 + fm) * Kn + other) * Ln + l0 + fh * 16;
#pragma unroll
        for (int e = 0; e < 4; e++)
            *(float4*)(&As[fm][fh * 16 + 4 * e]) = *(const float4*)(src + 4 * e);
        __syncthreads();

        float uval[4];
#pragma unroll
        for (int ni = 0; ni < 4; ni++) uval[ni] = uB[(size_t)other * Dn + dcol[ni]];

#pragma unroll
        for (int k0 = 0; k0 < 32; k0 += 8) {
            uint32_t b0[4], b1[4];
#pragma unroll
            for (int ni = 0; ni < 4; ni++) {
                float w0 = wT[(size_t)(l0 + k0 + q) * Dn + dcol[ni]];
                float w1 = wT[(size_t)(l0 + k0 + q + 4) * Dn + dcol[ni]];
                b0[ni] = tf32r(uval[ni] * w0);
                b1[ni] = tf32r(uval[ni] * w1);
            }
#pragma unroll
            for (int mi = 0; mi < 2; mi++) {
                int mb = wm * 32 + mi * 16;
                uint32_t a0 = __float_as_uint(As[mb + grp][k0 + q]);
                uint32_t a1 = __float_as_uint(As[mb + 8 + grp][k0 + q]);
                uint32_t a2 = __float_as_uint(As[mb + grp][k0 + q + 4]);
                uint32_t a3 = __float_as_uint(As[mb + 8 + grp][k0 + q + 4]);
#pragma unroll
                for (int ni = 0; ni < 4; ni++)
                    mma8(acc[mi][ni], a0, a1, a2, a3, b0[ni], b1[ni]);
            }
        }
        __syncthreads();
    }
    float* dst = g_part[mode * 4 + split];
#pragma unroll
    for (int mi = 0; mi < 2; mi++) {
        int r0 = m0 + wm * 32 + mi * 16 + grp;
#pragma unroll
        for (int ni = 0; ni < 4; ni++) {
            int c = d0 + wn * 32 + ni * 8 + 2 * q;
            dst[((size_t)b * Kn + r0) * Dn + c]           = acc[mi][ni][0];
            dst[((size_t)b * Kn + r0) * Dn + c + 1]       = acc[mi][ni][1];
            dst[((size_t)b * Kn + r0 + 8) * Dn + c]       = acc[mi][ni][2];
            dst[((size_t)b * Kn + r0 + 8) * Dn + c + 1]   = acc[mi][ni][3];
        }
    }
}

__global__ void combine_kernel(const float* __restrict__ slen) {
    int i = blockIdx.x * blockDim.x + threadIdx.x;
    if (i < BKD) {
        int b = i / (Kn * Dn);
        float s = 0.f;
#pragma unroll
        for (int p = 0; p < 8; p++) s += g_part[p][i];
        g_c[i] = s * (1.0f / slen[b]);
    }
}

// ---------------- gate GEMM: g = sigmoid([u|c] @ gate_w^T + gate_b) --------
__global__ __launch_bounds__(256) void gate_kernel(const float* __restrict__ u,
        const float* __restrict__ gate_w, const float* __restrict__ gate_b) {
    __shared__ float As[128][36];
    const int tid = threadIdx.x;
    const int warp = tid >> 5, lane = tid & 31;
    const int wm = warp & 3, wn = warp >> 2;
    const int grp = lane >> 2, q = lane & 3;
    const int m0 = blockIdx.x * 128, n0 = blockIdx.y * 64;
    const int fm = tid >> 1, fh = tid & 1;
    float acc[2][4][4] = {};

    for (int kb = 0; kb < 2 * Dn; kb += 32) {
        const float* src = (kb < Dn)
            ? u   + (size_t)(m0 + fm) * Dn + kb + fh * 16
            : g_c + (size_t)(m0 + fm) * Dn + (kb - Dn) + fh * 16;
#pragma unroll
        for (int e = 0; e < 4; e++) {
            float4 v = *(const float4*)(src + 4 * e);
            int c = fh * 16 + 4 * e;
            As[fm][c + 0] = tf32rf(v.x); As[fm][c + 1] = tf32rf(v.y);
            As[fm][c + 2] = tf32rf(v.z); As[fm][c + 3] = tf32rf(v.w);
        }
        __syncthreads();
#pragma unroll
        for (int k0 = 0; k0 < 32; k0 += 8) {
            uint32_t b0[4], b1[4];
#pragma unroll
            for (int ni = 0; ni < 4; ni++) {
                int n = n0 + wn * 32 + ni * 8 + grp;
                b0[ni] = tf32r(gate_w[(size_t)n * (2 * Dn) + kb + k0 + q]);
                b1[ni] = tf32r(gate_w[(size_t)n * (2 * Dn) + kb + k0 + q + 4]);
            }
#pragma unroll
            for (int mi = 0; mi < 2; mi++) {
                int mb = wm * 32 + mi * 16;
                uint32_t a0 = __float_as_uint(As[mb + grp][k0 + q]);
                uint32_t a1 = __float_as_uint(As[mb + 8 + grp][k0 + q]);
                uint32_t a2 = __float_as_uint(As[mb + grp][k0 + q + 4]);
                uint32_t a3 = __float_as_uint(As[mb + 8 + grp][k0 + q + 4]);
#pragma unroll
                for (int ni = 0; ni < 4; ni++)
                    mma8(acc[mi][ni], a0, a1, a2, a3, b0[ni], b1[ni]);
            }
        }
        __syncthreads();
    }
#pragma unroll
    for (int mi = 0; mi < 2; mi++) {
        int r0 = m0 + wm * 32 + mi * 16 + grp;
#pragma unroll
        for (int ni = 0; ni < 4; ni++) {
            int c = n0 + wn * 32 + ni * 8 + 2 * q;
            g_gate[(size_t)r0 * Dn + c]         = sigmoidf(acc[mi][ni][0] + gate_b[c]);
            g_gate[(size_t)r0 * Dn + c + 1]     = sigmoidf(acc[mi][ni][1] + gate_b[c + 1]);
            g_gate[(size_t)(r0 + 8) * Dn + c]     = sigmoidf(acc[mi][ni][2] + gate_b[c]);
            g_gate[(size_t)(r0 + 8) * Dn + c + 1] = sigmoidf(acc[mi][ni][3] + gate_b[c + 1]);
        }
    }
}

__global__ void update_kernel(float* __restrict__ u) {
    int i = blockIdx.x * blockDim.x + threadIdx.x;
    if (i < BKD) {
        float g = g_gate[i];
        u[i] = g * u[i] + (1.0f - g) * g_c[i];
    }
}

__global__ void scatter_kernel(const int* __restrict__ prune, const float* __restrict__ slen,
                               const float* __restrict__ u, float* __restrict__ outAll) {
    int i = blockIdx.x * blockDim.x + threadIdx.x;
    if (i < BKD) {
        int d = i % Dn, bk = i / Dn, b = bk / Kn, k = bk % Kn;
        if ((float)k < slen[b]) {
            int row = prune[bk];
            outAll[((size_t)b * Nn + row) * Dn + d] = u[i];
        }
    }
}

// ---------------- driver ---------------------------------------------------
extern "C" void kernel_launch(void* const* d_in, const int* in_sizes, int n_in,
                              void* d_out, int out_size) {
    (void)in_sizes; (void)n_in; (void)out_size;
    const float* all_vecs  = (const float*)d_in[0];
    const float* span_vecs = (const float*)d_in[1];
    const int*   span_beg  = (const int*)  d_in[2];
    const int*   span_end  = (const int*)  d_in[3];
    const float* mask      = (const float*)d_in[4];
    const float* slen      = (const float*)d_in[5];
    const int*   prune     = (const int*)  d_in[6];
    const float* left_w    = (const float*)d_in[7];
    const float* left_b    = (const float*)d_in[8];
    const float* right_w   = (const float*)d_in[9];
    const float* right_b   = (const float*)d_in[10];
    const float* dist_emb  = (const float*)d_in[11];
    const float* out_w     = (const float*)d_in[12];
    const float* out_b     = (const float*)d_in[13];
    const float* A_w       = (const float*)d_in[14];
    const float* B_w       = (const float*)d_in[15];
    const float* gate_w    = (const float*)d_in[16];
    const float* gate_b    = (const float*)d_in[17];

    float* outAll = (float*)d_out;           // [B,N,D]
    float* outU   = outAll + BND;            // [B,K,D]
    float* outS   = outU + BKD;              // [B,K,K,L]

    prep_kernel<<<(Ln * Dn + 255) / 256, 256>>>(out_w, A_w, B_w);
    copy_init_kernel<<<(BND + 255) / 256, 256>>>(all_vecs, span_vecs, outAll, outU);

    proj_kernel<<<dim3(4, 8), 256>>>(outU, left_w, left_b, right_w, right_b);
    scores_kernel<<<dim3(2, Kn, Bn), 256>>>(span_beg, span_end, dist_emb, out_b, mask, outS);

    for (int t = 0; t < 3; t++) {
        ctxt_kernel<<<dim3(2, 12, 16), 256>>>(outU);
        combine_kernel<<<(BKD + 255) / 256, 256>>>(slen);
        gate_kernel<<<dim3(4, 12), 256>>>(outU, gate_w, gate_b);
        update_kernel<<<(BKD + 255) / 256, 256>>>(outU);
        proj_kernel<<<dim3(4, 8), 256>>>(outU, left_w, left_b, right_w, right_b);
        scores_kernel<<<dim3(2, Kn, Bn), 256>>>(span_beg, span_end, dist_emb, out_b, mask, outS);
    }

    scatter_kernel<<<(BKD + 255) / 256, 256>>>(prune, slen, outU, outAll);
}

// round 3
// speedup vs baseline: 2.2408x; 1.2539x over previous
#include <cuda_runtime.h>
#include <cstdint>

#define Bn 2
#define Nn 2048
#define Kn 256
#define Dn 768
#define Hn 256
#define Ln 64
#define BND (Bn*Nn*Dn)
#define BKD (Bn*Kn*Dn)
#define BKH (Bn*Kn*Hn)
#define BKKL ((size_t)Bn*Kn*Kn*Ln)

// ---------------- scratch (device globals; no allocations allowed) ----------
__device__ float g_left [BKH];
__device__ float g_right[BKH];
__device__ float g_outwT[Hn*Ln];      // [h][l], tf32-rounded
__device__ float g_AwT  [Ln*Dn];      // [l][d], tf32-rounded
__device__ float g_BwT  [Ln*Dn];      // [l][d], tf32-rounded
__device__ float g_probs[BKKL];       // sigmoid(score)*mask, tf32-rounded
__device__ float g_part [8][BKD];     // (mode*4+split) partial contexts
__device__ float g_c    [BKD];
__device__ float g_gate [BKD];

__device__ __forceinline__ float sigmoidf(float x) {
    return 1.0f / (1.0f + __expf(-x));
}
__device__ __forceinline__ uint32_t tf32r(float x) {
    uint32_t u; asm("cvt.rna.tf32.f32 %0, %1;" : "=r"(u) : "f"(x)); return u;
}
__device__ __forceinline__ float tf32rf(float x) {
    return __uint_as_float(tf32r(x));
}
__device__ __forceinline__ void mma8(float c[4], uint32_t a0, uint32_t a1, uint32_t a2,
                                     uint32_t a3, uint32_t b0, uint32_t b1) {
    asm("mma.sync.aligned.m16n8k8.row.col.f32.tf32.tf32.f32 "
        "{%0,%1,%2,%3},{%4,%5,%6,%7},{%8,%9},{%0,%1,%2,%3};"
        : "+f"(c[0]), "+f"(c[1]), "+f"(c[2]), "+f"(c[3])
        : "r"(a0), "r"(a1), "r"(a2), "r"(a3), "r"(b0), "r"(b1));
}

// ---------------- prep: tf32-rounded weight transposes ---------------------
__global__ void prep_kernel(const float* __restrict__ out_w,
                            const float* __restrict__ A_w,
                            const float* __restrict__ B_w) {
    int i = blockIdx.x * blockDim.x + threadIdx.x;
    if (i < Hn * Ln) { int h = i / Ln, l = i - h * Ln; g_outwT[i] = tf32rf(out_w[l * Hn + h]); }
    if (i < Ln * Dn) { int l = i / Dn, d = i - l * Dn; g_AwT[i] = tf32rf(A_w[d * Ln + l]);
                                                      g_BwT[i] = tf32rf(B_w[d * Ln + l]); }
}

__global__ void copy_init_kernel(const float* __restrict__ all_vecs,
                                 const float* __restrict__ span_vecs,
                                 float* __restrict__ outAll,
                                 float* __restrict__ outU) {
    int i = blockIdx.x * blockDim.x + threadIdx.x;
    if (i < BND) outAll[i] = all_vecs[i];
    if (i < BKD) outU[i]   = span_vecs[i];
}

// ---------------- proj: [512 x 512] = u @ [left_w | right_w]^T -------------
__global__ __launch_bounds__(256) void proj_kernel(const float* __restrict__ u,
        const float* __restrict__ left_w,  const float* __restrict__ left_b,
        const float* __restrict__ right_w, const float* __restrict__ right_b) {
    __shared__ float As[128][36];
    const int tid = threadIdx.x;
    const int warp = tid >> 5, lane = tid & 31;
    const int wm = warp & 3, wn = warp >> 2;
    const int grp = lane >> 2, q = lane & 3;
    const int m0 = blockIdx.x * 128, n0 = blockIdx.y * 64;
    const bool isL = (n0 < Hn);
    const float* W    = isL ? left_w : right_w;
    const float* bias = isL ? left_b : right_b;
    float* OUT        = isL ? g_left : g_right;
    const int nloc0 = isL ? n0 : n0 - Hn;
    const int fm = tid >> 1, fh = tid & 1;
    float acc[2][4][4] = {};

    for (int kb = 0; kb < Dn; kb += 32) {
        const float* src = u + (size_t)(m0 + fm) * Dn + kb + fh * 16;
#pragma unroll
        for (int e = 0; e < 4; e++) {
            float4 v = *(const float4*)(src + 4 * e);
            int c = fh * 16 + 4 * e;
            As[fm][c + 0] = tf32rf(v.x); As[fm][c + 1] = tf32rf(v.y);
            As[fm][c + 2] = tf32rf(v.z); As[fm][c + 3] = tf32rf(v.w);
        }
        __syncthreads();
#pragma unroll
        for (int k0 = 0; k0 < 32; k0 += 8) {
            uint32_t b0[4], b1[4];
#pragma unroll
            for (int ni = 0; ni < 4; ni++) {
                int n = nloc0 + wn * 32 + ni * 8 + grp;
                b0[ni] = tf32r(W[(size_t)n * Dn + kb + k0 + q]);
                b1[ni] = tf32r(W[(size_t)n * Dn + kb + k0 + q + 4]);
            }
#pragma unroll
            for (int mi = 0; mi < 2; mi++) {
                int mb = wm * 32 + mi * 16;
                uint32_t a0 = __float_as_uint(As[mb + grp][k0 + q]);
                uint32_t a1 = __float_as_uint(As[mb + 8 + grp][k0 + q]);
                uint32_t a2 = __float_as_uint(As[mb + grp][k0 + q + 4]);
                uint32_t a3 = __float_as_uint(As[mb + 8 + grp][k0 + q + 4]);
#pragma unroll
                for (int ni = 0; ni < 4; ni++)
                    mma8(acc[mi][ni], a0, a1, a2, a3, b0[ni], b1[ni]);
            }
        }
        __syncthreads();
    }
#pragma unroll
    for (int mi = 0; mi < 2; mi++) {
        int r0 = m0 + wm * 32 + mi * 16 + grp;
#pragma unroll
        for (int ni = 0; ni < 4; ni++) {
            int c = nloc0 + wn * 32 + ni * 8 + 2 * q;
            OUT[(size_t)r0 * Hn + c]       = acc[mi][ni][0] + bias[c];
            OUT[(size_t)r0 * Hn + c + 1]   = acc[mi][ni][1] + bias[c + 1];
            OUT[(size_t)(r0 + 8) * Hn + c]     = acc[mi][ni][2] + bias[c];
            OUT[(size_t)(r0 + 8) * Hn + c + 1] = acc[mi][ni][3] + bias[c + 1];
        }
    }
}

// ---------------- fused pair-scorer + probs -------------------------------
// grid: (j-tile of 128, i, b). M=j(128), N=l(64), K=h(256)
__global__ __launch_bounds__(256) void scores_kernel(
        const int* __restrict__ span_begin, const int* __restrict__ span_end,
        const float* __restrict__ dist_emb, const float* __restrict__ out_b,
        const float* __restrict__ mask, float* __restrict__ scores) {
    __shared__ float As[128][36];
    __shared__ float oS[32][72];     // staged out_wT chunk [k][l]
    __shared__ float leftS[Hn];
    const int tid = threadIdx.x;
    const int warp = tid >> 5, lane = tid & 31;
    const int wm = warp & 3, wn = warp >> 2;
    const int grp = lane >> 2, q = lane & 3;
    const int b = blockIdx.z, i = blockIdx.y, j0 = blockIdx.x * 128;
    const int fm = tid >> 1, fh = tid & 1;
    const int fn = tid & 63, fk = tid >> 6;   // B-stage fill coords

    leftS[tid] = g_left[(size_t)(b * Kn + i) * Hn + tid];
    int dd = span_begin[b * Kn + j0 + fm] - span_end[b * Kn + i];
    int ad = abs(dd); const int bkt = ad > 63 ? 63 : ad;
    __syncthreads();

    float acc[2][4][4] = {};
    for (int hb = 0; hb < Hn; hb += 32) {
        const float* rsrc = g_right + (size_t)(b * Kn + j0 + fm) * Hn + hb + fh * 16;
        const float* dsrc = dist_emb + (size_t)bkt * Hn + hb + fh * 16;
#pragma unroll
        for (int e = 0; e < 4; e++) {
            float4 rv = *(const float4*)(rsrc + 4 * e);
            float4 dv = *(const float4*)(dsrc + 4 * e);
            int c = fh * 16 + 4 * e;
            float4 lv = *(const float4*)(&leftS[hb + c]);
            As[fm][c + 0] = tf32rf(fmaxf(lv.x + rv.x + dv.x, 0.f));
            As[fm][c + 1] = tf32rf(fmaxf(lv.y + rv.y + dv.y, 0.f));
            As[fm][c + 2] = tf32rf(fmaxf(lv.z + rv.z + dv.z, 0.f));
            As[fm][c + 3] = tf32rf(fmaxf(lv.w + rv.w + dv.w, 0.f));
        }
#pragma unroll
        for (int e = 0; e < 8; e++)
            oS[fk * 8 + e][fn] = g_outwT[(size_t)(hb + fk * 8 + e) * Ln + fn];
        __syncthreads();
#pragma unroll
        for (int k0 = 0; k0 < 32; k0 += 8) {
            uint32_t b0[4], b1[4];
#pragma unroll
            for (int ni = 0; ni < 4; ni++) {
                int n = wn * 32 + ni * 8 + grp;
                b0[ni] = __float_as_uint(oS[k0 + q][n]);
                b1[ni] = __float_as_uint(oS[k0 + q + 4][n]);
            }
#pragma unroll
            for (int mi = 0; mi < 2; mi++) {
                int mb = wm * 32 + mi * 16;
                uint32_t a0 = __float_as_uint(As[mb + grp][k0 + q]);
                uint32_t a1 = __float_as_uint(As[mb + 8 + grp][k0 + q]);
                uint32_t a2 = __float_as_uint(As[mb + grp][k0 + q + 4]);
                uint32_t a3 = __float_as_uint(As[mb + 8 + grp][k0 + q + 4]);
#pragma unroll
                for (int ni = 0; ni < 4; ni++)
                    mma8(acc[mi][ni], a0, a1, a2, a3, b0[ni], b1[ni]);
            }
        }
        __syncthreads();
    }
    float* scRow = scores + (size_t)(b * Kn + i) * (Kn * Ln);
    float* prRow = g_probs + (size_t)(b * Kn + i) * (Kn * Ln);
    const float* mkRow = mask + (size_t)(b * Kn + i) * Kn;
#pragma unroll
    for (int mi = 0; mi < 2; mi++) {
        int j0l = wm * 32 + mi * 16 + grp;
        float mk0 = mkRow[j0 + j0l], mk1 = mkRow[j0 + j0l + 8];
#pragma unroll
        for (int ni = 0; ni < 4; ni++) {
            int c = wn * 32 + ni * 8 + 2 * q;
#pragma unroll
            for (int e = 0; e < 2; e++) {
                float s0 = acc[mi][ni][e]     + out_b[c + e];
                float s1 = acc[mi][ni][2 + e] + out_b[c + e];
                scRow[(size_t)(j0 + j0l) * Ln + c + e]     = s0;
                scRow[(size_t)(j0 + j0l + 8) * Ln + c + e] = s1;
                prRow[(size_t)(j0 + j0l) * Ln + c + e]     = tf32rf(sigmoidf(s0) * mk0);
                prRow[(size_t)(j0 + j0l + 8) * Ln + c + e] = tf32rf(sigmoidf(s1) * mk1);
            }
        }
    }
}

// ---------------- context GEMMs -------------------------------------------
// mode 0: ctxt1[b,j,d] += probs[b,i,j,l] * u[b,i,d] * AwT[l,d]   (r=(i,l))
// mode 1: ctxt2[b,i,d] += probs[b,i,j,l] * u[b,j,d] * BwT[l,d]   (r=(j,l))
// grid: x=m-tile(2), y=d-tile(12), z = b*8 + mode*4 + split
__global__ __launch_bounds__(256) void ctxt_kernel(const float* __restrict__ u) {
    __shared__ float As[128][36];
    __shared__ float Bs[32][72];     // constructed tf32(u*w) tile [k][d]
    __shared__ float wS[64][68];     // staged weight slice [l][d]
    const int tid = threadIdx.x;
    const int warp = tid >> 5, lane = tid & 31;
    const int wm = warp & 3, wn = warp >> 2;
    const int grp = lane >> 2, q = lane & 3;
    const int z = blockIdx.z;
    const int b = z >> 3, mode = (z >> 2) & 1, split = z & 3;
    const int m0 = blockIdx.x * 128, d0 = blockIdx.y * 64;
    const float* wT = (mode == 0) ? g_AwT : g_BwT;
    const float* probsB = g_probs + (size_t)b * Kn * Kn * Ln;
    const float* uB     = u       + (size_t)b * Kn * Dn;
    const int fm = tid >> 1, fh = tid & 1;
    const int fd = tid & 63, fk = tid >> 6;   // B-construct coords

    // stage weight slice [64 l][64 d] once per block
    {
        int l = tid >> 2, c4 = (tid & 3) * 16;
#pragma unroll
        for (int e = 0; e < 4; e++)
            *(float4*)(&wS[l][c4 + 4 * e]) = *(const float4*)(&wT[(size_t)l * Dn + d0 + c4 + 4 * e]);
    }
    __syncthreads();

    float acc[2][4][4] = {};
    const int rBeg = split * 4096, rEnd = rBeg + 4096;
    for (int rb = rBeg; rb < rEnd; rb += 32) {
        const int other = rb >> 6;
        const int l0 = rb & 63;
        // A tile: probs (already tf32) -> smem
        const float* src = (mode == 0)
            ? probsB + ((size_t)other * Kn + m0 + fm) * Ln + l0 + fh * 16
            : probsB + ((size_t)(m0 + fm) * Kn + other) * Ln + l0 + fh * 16;
#pragma unroll
        for (int e = 0; e < 4; e++)
            *(float4*)(&As[fm][fh * 16 + 4 * e]) = *(const float4*)(src + 4 * e);
        // B tile: cooperatively build tf32(u[other,d] * w[l0+k][d])
        {
            float uval = uB[(size_t)other * Dn + d0 + fd];
#pragma unroll
            for (int e = 0; e < 8; e++) {
                int k = fk * 8 + e;
                Bs[k][fd] = tf32rf(uval * wS[l0 + k][fd]);
            }
        }
        __syncthreads();
#pragma unroll
        for (int k0 = 0; k0 < 32; k0 += 8) {
            uint32_t b0[4], b1[4];
#pragma unroll
            for (int ni = 0; ni < 4; ni++) {
                int n = wn * 32 + ni * 8 + grp;
                b0[ni] = __float_as_uint(Bs[k0 + q][n]);
                b1[ni] = __float_as_uint(Bs[k0 + q + 4][n]);
            }
#pragma unroll
            for (int mi = 0; mi < 2; mi++) {
                int mb = wm * 32 + mi * 16;
                uint32_t a0 = __float_as_uint(As[mb + grp][k0 + q]);
                uint32_t a1 = __float_as_uint(As[mb + 8 + grp][k0 + q]);
                uint32_t a2 = __float_as_uint(As[mb + grp][k0 + q + 4]);
                uint32_t a3 = __float_as_uint(As[mb + 8 + grp][k0 + q + 4]);
#pragma unroll
                for (int ni = 0; ni < 4; ni++)
                    mma8(acc[mi][ni], a0, a1, a2, a3, b0[ni], b1[ni]);
            }
        }
        __syncthreads();
    }
    float* dst = g_part[mode * 4 + split];
#pragma unroll
    for (int mi = 0; mi < 2; mi++) {
        int r0 = m0 + wm * 32 + mi * 16 + grp;
#pragma unroll
        for (int ni = 0; ni < 4; ni++) {
            int c = d0 + wn * 32 + ni * 8 + 2 * q;
            dst[((size_t)b * Kn + r0) * Dn + c]           = acc[mi][ni][0];
            dst[((size_t)b * Kn + r0) * Dn + c + 1]       = acc[mi][ni][1];
            dst[((size_t)b * Kn + r0 + 8) * Dn + c]       = acc[mi][ni][2];
            dst[((size_t)b * Kn + r0 + 8) * Dn + c + 1]   = acc[mi][ni][3];
        }
    }
}

__global__ void combine_kernel(const float* __restrict__ slen) {
    int i = blockIdx.x * blockDim.x + threadIdx.x;
    if (i < BKD) {
        int b = i / (Kn * Dn);
        float s = 0.f;
#pragma unroll
        for (int p = 0; p < 8; p++) s += g_part[p][i];
        g_c[i] = s * (1.0f / slen[b]);
    }
}

// ---------------- gate GEMM: g = sigmoid([u|c] @ gate_w^T + gate_b) --------
__global__ __launch_bounds__(256) void gate_kernel(const float* __restrict__ u,
        const float* __restrict__ gate_w, const float* __restrict__ gate_b) {
    __shared__ float As[128][36];
    const int tid = threadIdx.x;
    const int warp = tid >> 5, lane = tid & 31;
    const int wm = warp & 3, wn = warp >> 2;
    const int grp = lane >> 2, q = lane & 3;
    const int m0 = blockIdx.x * 128, n0 = blockIdx.y * 64;
    const int fm = tid >> 1, fh = tid & 1;
    float acc[2][4][4] = {};

    for (int kb = 0; kb < 2 * Dn; kb += 32) {
        const float* src = (kb < Dn)
            ? u   + (size_t)(m0 + fm) * Dn + kb + fh * 16
            : g_c + (size_t)(m0 + fm) * Dn + (kb - Dn) + fh * 16;
#pragma unroll
        for (int e = 0; e < 4; e++) {
            float4 v = *(const float4*)(src + 4 * e);
            int c = fh * 16 + 4 * e;
            As[fm][c + 0] = tf32rf(v.x); As[fm][c + 1] = tf32rf(v.y);
            As[fm][c + 2] = tf32rf(v.z); As[fm][c + 3] = tf32rf(v.w);
        }
        __syncthreads();
#pragma unroll
        for (int k0 = 0; k0 < 32; k0 += 8) {
            uint32_t b0[4], b1[4];
#pragma unroll
            for (int ni = 0; ni < 4; ni++) {
                int n = n0 + wn * 32 + ni * 8 + grp;
                b0[ni] = tf32r(gate_w[(size_t)n * (2 * Dn) + kb + k0 + q]);
                b1[ni] = tf32r(gate_w[(size_t)n * (2 * Dn) + kb + k0 + q + 4]);
            }
#pragma unroll
            for (int mi = 0; mi < 2; mi++) {
                int mb = wm * 32 + mi * 16;
                uint32_t a0 = __float_as_uint(As[mb + grp][k0 + q]);
                uint32_t a1 = __float_as_uint(As[mb + 8 + grp][k0 + q]);
                uint32_t a2 = __float_as_uint(As[mb + grp][k0 + q + 4]);
                uint32_t a3 = __float_as_uint(As[mb + 8 + grp][k0 + q + 4]);
#pragma unroll
                for (int ni = 0; ni < 4; ni++)
                    mma8(acc[mi][ni], a0, a1, a2, a3, b0[ni], b1[ni]);
            }
        }
        __syncthreads();
    }
#pragma unroll
    for (int mi = 0; mi < 2; mi++) {
        int r0 = m0 + wm * 32 + mi * 16 + grp;
#pragma unroll
        for (int ni = 0; ni < 4; ni++) {
            int c = n0 + wn * 32 + ni * 8 + 2 * q;
            g_gate[(size_t)r0 * Dn + c]         = sigmoidf(acc[mi][ni][0] + gate_b[c]);
            g_gate[(size_t)r0 * Dn + c + 1]     = sigmoidf(acc[mi][ni][1] + gate_b[c + 1]);
            g_gate[(size_t)(r0 + 8) * Dn + c]     = sigmoidf(acc[mi][ni][2] + gate_b[c]);
            g_gate[(size_t)(r0 + 8) * Dn + c + 1] = sigmoidf(acc[mi][ni][3] + gate_b[c + 1]);
        }
    }
}

__global__ void update_kernel(float* __restrict__ u) {
    int i = blockIdx.x * blockDim.x + threadIdx.x;
    if (i < BKD) {
        float g = g_gate[i];
        u[i] = g * u[i] + (1.0f - g) * g_c[i];
    }
}

__global__ void scatter_kernel(const int* __restrict__ prune, const float* __restrict__ slen,
                               const float* __restrict__ u, float* __restrict__ outAll) {
    int i = blockIdx.x * blockDim.x + threadIdx.x;
    if (i < BKD) {
        int d = i % Dn, bk = i / Dn, b = bk / Kn, k = bk % Kn;
        if ((float)k < slen[b]) {
            int row = prune[bk];
            outAll[((size_t)b * Nn + row) * Dn + d] = u[i];
        }
    }
}

// ---------------- driver ---------------------------------------------------
extern "C" void kernel_launch(void* const* d_in, const int* in_sizes, int n_in,
                              void* d_out, int out_size) {
    (void)in_sizes; (void)n_in; (void)out_size;
    const float* all_vecs  = (const float*)d_in[0];
    const float* span_vecs = (const float*)d_in[1];
    const int*   span_beg  = (const int*)  d_in[2];
    const int*   span_end  = (const int*)  d_in[3];
    const float* mask      = (const float*)d_in[4];
    const float* slen      = (const float*)d_in[5];
    const int*   prune     = (const int*)  d_in[6];
    const float* left_w    = (const float*)d_in[7];
    const float* left_b    = (const float*)d_in[8];
    const float* right_w   = (const float*)d_in[9];
    const float* right_b   = (const float*)d_in[10];
    const float* dist_emb  = (const float*)d_in[11];
    const float* out_w     = (const float*)d_in[12];
    const float* out_b     = (const float*)d_in[13];
    const float* A_w       = (const float*)d_in[14];
    const float* B_w       = (const float*)d_in[15];
    const float* gate_w    = (const float*)d_in[16];
    const float* gate_b    = (const float*)d_in[17];

    float* outAll = (float*)d_out;           // [B,N,D]
    float* outU   = outAll + BND;            // [B,K,D]
    float* outS   = outU + BKD;              // [B,K,K,L]

    prep_kernel<<<(Ln * Dn + 255) / 256, 256>>>(out_w, A_w, B_w);
    copy_init_kernel<<<(BND + 255) / 256, 256>>>(all_vecs, span_vecs, outAll, outU);

    proj_kernel<<<dim3(4, 8), 256>>>(outU, left_w, left_b, right_w, right_b);
    scores_kernel<<<dim3(2, Kn, Bn), 256>>>(span_beg, span_end, dist_emb, out_b, mask, outS);

    for (int t = 0; t < 3; t++) {
        ctxt_kernel<<<dim3(2, 12, 16), 256>>>(outU);
        combine_kernel<<<(BKD + 255) / 256, 256>>>(slen);
        gate_kernel<<<dim3(4, 12), 256>>>(outU, gate_w, gate_b);
        update_kernel<<<(BKD + 255) / 256, 256>>>(outU);
        proj_kernel<<<dim3(4, 8), 256>>>(outU, left_w, left_b, right_w, right_b);
        scores_kernel<<<dim3(2, Kn, Bn), 256>>>(span_beg, span_end, dist_emb, out_b, mask, outS);
    }

    scatter_kernel<<<(BKD + 255) / 256, 256>>>(prune, slen, outU, outAll);
}

// round 5
// speedup vs baseline: 2.2963x; 1.0248x over previous
#include <cuda_runtime.h>
#include <cstdint>

#define Bn 2
#define Nn 2048
#define Kn 256
#define Dn 768
#define Hn 256
#define Ln 64
#define BND (Bn*Nn*Dn)
#define BKD (Bn*Kn*Dn)
#define BKH (Bn*Kn*Hn)
#define BKKL ((size_t)Bn*Kn*Kn*Ln)

// ---------------- scratch (device globals; no allocations allowed) ----------
__device__ float g_left [BKH];
__device__ float g_right[BKH];
__device__ float g_outwT[Hn*Ln];      // [h][l], tf32-rounded
__device__ float g_AwT  [Ln*Dn];      // [l][d], tf32-rounded
__device__ float g_BwT  [Ln*Dn];      // [l][d], tf32-rounded
__device__ float g_probs[BKKL];       // sigmoid(score)*mask, tf32-rounded
__device__ float g_part [8][BKD];     // (mode*4+split) partial contexts
__device__ float g_c    [BKD];
__device__ float g_gate [BKD];

__device__ __forceinline__ float sigmoidf(float x) {
    return 1.0f / (1.0f + __expf(-x));
}
__device__ __forceinline__ uint32_t tf32r(float x) {
    uint32_t u; asm("cvt.rna.tf32.f32 %0, %1;" : "=r"(u) : "f"(x)); return u;
}
__device__ __forceinline__ float tf32rf(float x) {
    return __uint_as_float(tf32r(x));
}
__device__ __forceinline__ void mma8(float c[4], uint32_t a0, uint32_t a1, uint32_t a2,
                                     uint32_t a3, uint32_t b0, uint32_t b1) {
    asm("mma.sync.aligned.m16n8k8.row.col.f32.tf32.tf32.f32 "
        "{%0,%1,%2,%3},{%4,%5,%6,%7},{%8,%9},{%0,%1,%2,%3};"
        : "+f"(c[0]), "+f"(c[1]), "+f"(c[2]), "+f"(c[3])
        : "r"(a0), "r"(a1), "r"(a2), "r"(a3), "r"(b0), "r"(b1));
}

// ---------------- prep: tf32-rounded weight transposes ---------------------
__global__ void prep_kernel(const float* __restrict__ out_w,
                            const float* __restrict__ A_w,
                            const float* __restrict__ B_w) {
    int i = blockIdx.x * blockDim.x + threadIdx.x;
    if (i < Hn * Ln) { int h = i / Ln, l = i - h * Ln; g_outwT[i] = tf32rf(out_w[l * Hn + h]); }
    if (i < Ln * Dn) { int l = i / Dn, d = i - l * Dn; g_AwT[i] = tf32rf(A_w[d * Ln + l]);
                                                      g_BwT[i] = tf32rf(B_w[d * Ln + l]); }
}

__global__ void copy_init_kernel(const float* __restrict__ all_vecs,
                                 const float* __restrict__ span_vecs,
                                 float* __restrict__ outAll,
                                 float* __restrict__ outU) {
    int i = blockIdx.x * blockDim.x + threadIdx.x;
    if (i < BND) outAll[i] = all_vecs[i];
    if (i < BKD) outU[i]   = span_vecs[i];
}

// ---------------- proj: [512 x 512] = u @ [left_w | right_w]^T -------------
__global__ __launch_bounds__(256) void proj_kernel(const float* __restrict__ u,
        const float* __restrict__ left_w,  const float* __restrict__ left_b,
        const float* __restrict__ right_w, const float* __restrict__ right_b) {
    __shared__ float As[128][36];
    const int tid = threadIdx.x;
    const int warp = tid >> 5, lane = tid & 31;
    const int wm = warp & 3, wn = warp >> 2;
    const int grp = lane >> 2, q = lane & 3;
    const int m0 = blockIdx.x * 128, n0 = blockIdx.y * 64;
    const bool isL = (n0 < Hn);
    const float* W    = isL ? left_w : right_w;
    const float* bias = isL ? left_b : right_b;
    float* OUT        = isL ? g_left : g_right;
    const int nloc0 = isL ? n0 : n0 - Hn;
    const int fm = tid >> 1, fh = tid & 1;
    float acc[2][4][4] = {};

    for (int kb = 0; kb < Dn; kb += 32) {
        const float* src = u + (size_t)(m0 + fm) * Dn + kb + fh * 16;
#pragma unroll
        for (int e = 0; e < 4; e++) {
            float4 v = *(const float4*)(src + 4 * e);
            int c = fh * 16 + 4 * e;
            As[fm][c + 0] = tf32rf(v.x); As[fm][c + 1] = tf32rf(v.y);
            As[fm][c + 2] = tf32rf(v.z); As[fm][c + 3] = tf32rf(v.w);
        }
        __syncthreads();
#pragma unroll
        for (int k0 = 0; k0 < 32; k0 += 8) {
            uint32_t b0[4], b1[4];
#pragma unroll
            for (int ni = 0; ni < 4; ni++) {
                int n = nloc0 + wn * 32 + ni * 8 + grp;
                b0[ni] = tf32r(W[(size_t)n * Dn + kb + k0 + q]);
                b1[ni] = tf32r(W[(size_t)n * Dn + kb + k0 + q + 4]);
            }
#pragma unroll
            for (int mi = 0; mi < 2; mi++) {
                int mb = wm * 32 + mi * 16;
                uint32_t a0 = __float_as_uint(As[mb + grp][k0 + q]);
                uint32_t a1 = __float_as_uint(As[mb + 8 + grp][k0 + q]);
                uint32_t a2 = __float_as_uint(As[mb + grp][k0 + q + 4]);
                uint32_t a3 = __float_as_uint(As[mb + 8 + grp][k0 + q + 4]);
#pragma unroll
                for (int ni = 0; ni < 4; ni++)
                    mma8(acc[mi][ni], a0, a1, a2, a3, b0[ni], b1[ni]);
            }
        }
        __syncthreads();
    }
#pragma unroll
    for (int mi = 0; mi < 2; mi++) {
        int r0 = m0 + wm * 32 + mi * 16 + grp;
#pragma unroll
        for (int ni = 0; ni < 4; ni++) {
            int c = nloc0 + wn * 32 + ni * 8 + 2 * q;
            OUT[(size_t)r0 * Hn + c]       = acc[mi][ni][0] + bias[c];
            OUT[(size_t)r0 * Hn + c + 1]   = acc[mi][ni][1] + bias[c + 1];
            OUT[(size_t)(r0 + 8) * Hn + c]     = acc[mi][ni][2] + bias[c];
            OUT[(size_t)(r0 + 8) * Hn + c + 1] = acc[mi][ni][3] + bias[c + 1];
        }
    }
}

// ---------------- fused pair-scorer + probs (64x64 warp tiles) -------------
// block = 128 threads = 4 warps, block tile 256j x 64l, K = h(256)
// grid: (1, i=256, b=2)
__global__ __launch_bounds__(128) void scores_kernel(
        const int* __restrict__ span_begin, const int* __restrict__ span_end,
        const float* __restrict__ dist_emb, const float* __restrict__ out_b,
        const float* __restrict__ mask, float* __restrict__ scores) {
    __shared__ float As[256][36];
    __shared__ float Bs[32][72];
    __shared__ float leftS[Hn];
    __shared__ int   bktS[256];
    const int tid = threadIdx.x;
    const int warp = tid >> 5, lane = tid & 31;
    const int grp = lane >> 2, q = lane & 3;
    const int b = blockIdx.z, i = blockIdx.y;   // FIXED: matches grid (1, Kn, Bn)
    const int arow = tid >> 3, aq = tid & 7;      // A-fill coords (16 rows x 8 quads / pass)
    const int fd4 = (tid & 15) * 4, fkb = tid >> 4; // B-fill coords

    leftS[tid]       = g_left[(size_t)(b * Kn + i) * Hn + tid];
    leftS[tid + 128] = g_left[(size_t)(b * Kn + i) * Hn + tid + 128];
    const int iend = span_end[b * Kn + i];
#pragma unroll
    for (int e = 0; e < 2; e++) {
        int j = tid + e * 128;
        int ad = abs(span_begin[b * Kn + j] - iend);
        bktS[j] = ad > 63 ? 63 : ad;
    }
    __syncthreads();

    float acc[4][8][4] = {};
    for (int hb = 0; hb < Hn; hb += 32) {
        // A tile: relu(left + right + dist), tf32
#pragma unroll
        for (int p = 0; p < 16; p++) {
            int j = p * 16 + arow;
            float4 rv = *(const float4*)&g_right[(size_t)(b * Kn + j) * Hn + hb + aq * 4];
            float4 dv = *(const float4*)&dist_emb[(size_t)bktS[j] * Hn + hb + aq * 4];
            float4 lv = *(const float4*)&leftS[hb + aq * 4];
            float4 o;
            o.x = tf32rf(fmaxf(lv.x + rv.x + dv.x, 0.f));
            o.y = tf32rf(fmaxf(lv.y + rv.y + dv.y, 0.f));
            o.z = tf32rf(fmaxf(lv.z + rv.z + dv.z, 0.f));
            o.w = tf32rf(fmaxf(lv.w + rv.w + dv.w, 0.f));
            *(float4*)&As[j][aq * 4] = o;
        }
        // B tile: out_wT chunk (already tf32)
#pragma unroll
        for (int e = 0; e < 4; e++) {
            int k = fkb * 4 + e;
            *(float4*)&Bs[k][fd4] = *(const float4*)&g_outwT[(size_t)(hb + k) * Ln + fd4];
        }
        __syncthreads();
#pragma unroll
        for (int k0 = 0; k0 < 32; k0 += 8) {
            uint32_t b0[8], b1[8];
#pragma unroll
            for (int ni = 0; ni < 8; ni++) {
                int n = ni * 8 + grp;
                b0[ni] = __float_as_uint(Bs[k0 + q][n]);
                b1[ni] = __float_as_uint(Bs[k0 + q + 4][n]);
            }
#pragma unroll
            for (int mi = 0; mi < 4; mi++) {
                int mb = warp * 64 + mi * 16;
                uint32_t a0 = __float_as_uint(As[mb + grp][k0 + q]);
                uint32_t a1 = __float_as_uint(As[mb + 8 + grp][k0 + q]);
                uint32_t a2 = __float_as_uint(As[mb + grp][k0 + q + 4]);
                uint32_t a3 = __float_as_uint(As[mb + 8 + grp][k0 + q + 4]);
#pragma unroll
                for (int ni = 0; ni < 8; ni++)
                    mma8(acc[mi][ni], a0, a1, a2, a3, b0[ni], b1[ni]);
            }
        }
        __syncthreads();
    }
    float* scRow = scores + (size_t)(b * Kn + i) * (Kn * Ln);
    float* prRow = g_probs + (size_t)(b * Kn + i) * (Kn * Ln);
    const float* mkRow = mask + (size_t)(b * Kn + i) * Kn;
#pragma unroll
    for (int mi = 0; mi < 4; mi++) {
        int j = warp * 64 + mi * 16 + grp;
        float mk0 = mkRow[j], mk1 = mkRow[j + 8];
#pragma unroll
        for (int ni = 0; ni < 8; ni++) {
            int c = ni * 8 + 2 * q;
            float ob0 = out_b[c], ob1 = out_b[c + 1];
            float s00 = acc[mi][ni][0] + ob0, s01 = acc[mi][ni][1] + ob1;
            float s10 = acc[mi][ni][2] + ob0, s11 = acc[mi][ni][3] + ob1;
            *(float2*)&scRow[(size_t)j * Ln + c]       = make_float2(s00, s01);
            *(float2*)&scRow[(size_t)(j + 8) * Ln + c] = make_float2(s10, s11);
            *(float2*)&prRow[(size_t)j * Ln + c] =
                make_float2(tf32rf(sigmoidf(s00) * mk0), tf32rf(sigmoidf(s01) * mk0));
            *(float2*)&prRow[(size_t)(j + 8) * Ln + c] =
                make_float2(tf32rf(sigmoidf(s10) * mk1), tf32rf(sigmoidf(s11) * mk1));
        }
    }
}

// ---------------- context GEMMs (64x64 warp tiles) -------------------------
// mode 0: ctxt1[b,j,d] += probs[b,i,j,l] * u[b,i,d] * AwT[l,d]   (r=(i,l))
// mode 1: ctxt2[b,i,d] += probs[b,i,j,l] * u[b,j,d] * BwT[l,d]   (r=(j,l))
// block = 128 threads = 4 warps, block tile 256m x 64d.
// grid: (1, d-tile=12, z = b*8 + mode*4 + split(4))
__global__ __launch_bounds__(128) void ctxt_kernel(const float* __restrict__ u) {
    __shared__ float As[256][36];
    __shared__ float Bs[32][72];
    const int tid = threadIdx.x;
    const int warp = tid >> 5, lane = tid & 31;
    const int grp = lane >> 2, q = lane & 3;
    const int z = blockIdx.z;
    const int b = z >> 3, mode = (z >> 2) & 1, split = z & 3;
    const int d0 = blockIdx.y * 64;
    const float* wT = (mode == 0) ? g_AwT : g_BwT;
    const float* probsB = g_probs + (size_t)b * Kn * Kn * Ln;
    const float* uB     = u       + (size_t)b * Kn * Dn;
    const int arow = tid >> 3, aq = tid & 7;
    const int fd4 = (tid & 15) * 4, fkb = tid >> 4;

    float acc[4][8][4] = {};
    const int rBeg = split * 4096, rEnd = rBeg + 4096;
    for (int rb = rBeg; rb < rEnd; rb += 32) {
        const int other = rb >> 6;
        const int l0 = rb & 63;
        // A tile: probs (already tf32) -> smem
#pragma unroll
        for (int p = 0; p < 16; p++) {
            int m = p * 16 + arow;
            const float* src = (mode == 0)
                ? &probsB[((size_t)other * Kn + m) * Ln + l0]
                : &probsB[((size_t)m * Kn + other) * Ln + l0];
            *(float4*)&As[m][aq * 4] = *(const float4*)(src + aq * 4);
        }
        // B tile: tf32(u[other,d] * w[l0+k][d]); w from gmem (L1-resident)
        {
            float4 uv = *(const float4*)&uB[(size_t)other * Dn + d0 + fd4];
#pragma unroll
            for (int e = 0; e < 4; e++) {
                int k = fkb * 4 + e;
                float4 wv = *(const float4*)&wT[(size_t)(l0 + k) * Dn + d0 + fd4];
                float4 o;
                o.x = tf32rf(uv.x * wv.x); o.y = tf32rf(uv.y * wv.y);
                o.z = tf32rf(uv.z * wv.z); o.w = tf32rf(uv.w * wv.w);
                *(float4*)&Bs[k][fd4] = o;
            }
        }
        __syncthreads();
#pragma unroll
        for (int k0 = 0; k0 < 32; k0 += 8) {
            uint32_t b0[8], b1[8];
#pragma unroll
            for (int ni = 0; ni < 8; ni++) {
                int n = ni * 8 + grp;
                b0[ni] = __float_as_uint(Bs[k0 + q][n]);
                b1[ni] = __float_as_uint(Bs[k0 + q + 4][n]);
            }
#pragma unroll
            for (int mi = 0; mi < 4; mi++) {
                int mb = warp * 64 + mi * 16;
                uint32_t a0 = __float_as_uint(As[mb + grp][k0 + q]);
                uint32_t a1 = __float_as_uint(As[mb + 8 + grp][k0 + q]);
                uint32_t a2 = __float_as_uint(As[mb + grp][k0 + q + 4]);
                uint32_t a3 = __float_as_uint(As[mb + 8 + grp][k0 + q + 4]);
#pragma unroll
                for (int ni = 0; ni < 8; ni++)
                    mma8(acc[mi][ni], a0, a1, a2, a3, b0[ni], b1[ni]);
            }
        }
        __syncthreads();
    }
    float* dst = g_part[mode * 4 + split];
#pragma unroll
    for (int mi = 0; mi < 4; mi++) {
        int r = warp * 64 + mi * 16 + grp;
#pragma unroll
        for (int ni = 0; ni < 8; ni++) {
            int c = d0 + ni * 8 + 2 * q;
            *(float2*)&dst[((size_t)b * Kn + r) * Dn + c] =
                make_float2(acc[mi][ni][0], acc[mi][ni][1]);
            *(float2*)&dst[((size_t)b * Kn + r + 8) * Dn + c] =
                make_float2(acc[mi][ni][2], acc[mi][ni][3]);
        }
    }
}

__global__ void combine_kernel(const float* __restrict__ slen) {
    int i = blockIdx.x * blockDim.x + threadIdx.x;
    if (i < BKD) {
        int b = i / (Kn * Dn);
        float s = 0.f;
#pragma unroll
        for (int p = 0; p < 8; p++) s += g_part[p][i];
        g_c[i] = s * (1.0f / slen[b]);
    }
}

// ---------------- gate GEMM: g = sigmoid([u|c] @ gate_w^T + gate_b) --------
__global__ __launch_bounds__(256) void gate_kernel(const float* __restrict__ u,
        const float* __restrict__ gate_w, const float* __restrict__ gate_b) {
    __shared__ float As[128][36];
    const int tid = threadIdx.x;
    const int warp = tid >> 5, lane = tid & 31;
    const int wm = warp & 3, wn = warp >> 2;
    const int grp = lane >> 2, q = lane & 3;
    const int m0 = blockIdx.x * 128, n0 = blockIdx.y * 64;
    const int fm = tid >> 1, fh = tid & 1;
    float acc[2][4][4] = {};

    for (int kb = 0; kb < 2 * Dn; kb += 32) {
        const float* src = (kb < Dn)
            ? u   + (size_t)(m0 + fm) * Dn + kb + fh * 16
            : g_c + (size_t)(m0 + fm) * Dn + (kb - Dn) + fh * 16;
#pragma unroll
        for (int e = 0; e < 4; e++) {
            float4 v = *(const float4*)(src + 4 * e);
            int c = fh * 16 + 4 * e;
            As[fm][c + 0] = tf32rf(v.x); As[fm][c + 1] = tf32rf(v.y);
            As[fm][c + 2] = tf32rf(v.z); As[fm][c + 3] = tf32rf(v.w);
        }
        __syncthreads();
#pragma unroll
        for (int k0 = 0; k0 < 32; k0 += 8) {
            uint32_t b0[4], b1[4];
#pragma unroll
            for (int ni = 0; ni < 4; ni++) {
                int n = n0 + wn * 32 + ni * 8 + grp;
                b0[ni] = tf32r(gate_w[(size_t)n * (2 * Dn) + kb + k0 + q]);
                b1[ni] = tf32r(gate_w[(size_t)n * (2 * Dn) + kb + k0 + q + 4]);
            }
#pragma unroll
            for (int mi = 0; mi < 2; mi++) {
                int mb = wm * 32 + mi * 16;
                uint32_t a0 = __float_as_uint(As[mb + grp][k0 + q]);
                uint32_t a1 = __float_as_uint(As[mb + 8 + grp][k0 + q]);
                uint32_t a2 = __float_as_uint(As[mb + grp][k0 + q + 4]);
                uint32_t a3 = __float_as_uint(As[mb + 8 + grp][k0 + q + 4]);
#pragma unroll
                for (int ni = 0; ni < 4; ni++)
                    mma8(acc[mi][ni], a0, a1, a2, a3, b0[ni], b1[ni]);
            }
        }
        __syncthreads();
    }
#pragma unroll
    for (int mi = 0; mi < 2; mi++) {
        int r0 = m0 + wm * 32 + mi * 16 + grp;
#pragma unroll
        for (int ni = 0; ni < 4; ni++) {
            int c = n0 + wn * 32 + ni * 8 + 2 * q;
            g_gate[(size_t)r0 * Dn + c]         = sigmoidf(acc[mi][ni][0] + gate_b[c]);
            g_gate[(size_t)r0 * Dn + c + 1]     = sigmoidf(acc[mi][ni][1] + gate_b[c + 1]);
            g_gate[(size_t)(r0 + 8) * Dn + c]     = sigmoidf(acc[mi][ni][2] + gate_b[c]);
            g_gate[(size_t)(r0 + 8) * Dn + c + 1] = sigmoidf(acc[mi][ni][3] + gate_b[c + 1]);
        }
    }
}

__global__ void update_kernel(float* __restrict__ u) {
    int i = blockIdx.x * blockDim.x + threadIdx.x;
    if (i < BKD) {
        float g = g_gate[i];
        u[i] = g * u[i] + (1.0f - g) * g_c[i];
    }
}

__global__ void scatter_kernel(const int* __restrict__ prune, const float* __restrict__ slen,
                               const float* __restrict__ u, float* __restrict__ outAll) {
    int i = blockIdx.x * blockDim.x + threadIdx.x;
    if (i < BKD) {
        int d = i % Dn, bk = i / Dn, b = bk / Kn, k = bk % Kn;
        if ((float)k < slen[b]) {
            int row = prune[bk];
            outAll[((size_t)b * Nn + row) * Dn + d] = u[i];
        }
    }
}

// ---------------- driver ---------------------------------------------------
extern "C" void kernel_launch(void* const* d_in, const int* in_sizes, int n_in,
                              void* d_out, int out_size) {
    (void)in_sizes; (void)n_in; (void)out_size;
    const float* all_vecs  = (const float*)d_in[0];
    const float* span_vecs = (const float*)d_in[1];
    const int*   span_beg  = (const int*)  d_in[2];
    const int*   span_end  = (const int*)  d_in[3];
    const float* mask      = (const float*)d_in[4];
    const float* slen      = (const float*)d_in[5];
    const int*   prune     = (const int*)  d_in[6];
    const float* left_w    = (const float*)d_in[7];
    const float* left_b    = (const float*)d_in[8];
    const float* right_w   = (const float*)d_in[9];
    const float* right_b   = (const float*)d_in[10];
    const float* dist_emb  = (const float*)d_in[11];
    const float* out_w     = (const float*)d_in[12];
    const float* out_b     = (const float*)d_in[13];
    const float* A_w       = (const float*)d_in[14];
    const float* B_w       = (const float*)d_in[15];
    const float* gate_w    = (const float*)d_in[16];
    const float* gate_b    = (const float*)d_in[17];

    float* outAll = (float*)d_out;           // [B,N,D]
    float* outU   = outAll + BND;            // [B,K,D]
    float* outS   = outU + BKD;              // [B,K,K,L]

    prep_kernel<<<(Ln * Dn + 255) / 256, 256>>>(out_w, A_w, B_w);
    copy_init_kernel<<<(BND + 255) / 256, 256>>>(all_vecs, span_vecs, outAll, outU);

    proj_kernel<<<dim3(4, 8), 256>>>(outU, left_w, left_b, right_w, right_b);
    scores_kernel<<<dim3(1, Kn, Bn), 128>>>(span_beg, span_end, dist_emb, out_b, mask, outS);

    for (int t = 0; t < 3; t++) {
        ctxt_kernel<<<dim3(1, 12, 16), 128>>>(outU);
        combine_kernel<<<(BKD + 255) / 256, 256>>>(slen);
        gate_kernel<<<dim3(4, 12), 256>>>(outU, gate_w, gate_b);
        update_kernel<<<(BKD + 255) / 256, 256>>>(outU);
        proj_kernel<<<dim3(4, 8), 256>>>(outU, left_w, left_b, right_w, right_b);
        scores_kernel<<<dim3(1, Kn, Bn), 128>>>(span_beg, span_end, dist_emb, out_b, mask, outS);
    }

    scatter_kernel<<<(BKD + 255) / 256, 256>>>(prune, slen, outU, outAll);
}

// round 6
// speedup vs baseline: 2.5835x; 1.1251x over previous
#include <cuda_runtime.h>
#include <cstdint>

#define Bn 2
#define Nn 2048
#define Kn 256
#define Dn 768
#define Hn 256
#define Ln 64
#define BND (Bn*Nn*Dn)
#define BKD (Bn*Kn*Dn)
#define BKH (Bn*Kn*Hn)
#define BKKL ((size_t)Bn*Kn*Kn*Ln)

// ---------------- scratch (device globals; no allocations allowed) ----------
__device__ float g_left [BKH];
__device__ float g_right[BKH];
__device__ float g_outwT[Hn*Ln];      // [h][l], tf32-rounded
__device__ float g_AwT  [Ln*Dn];      // [l][d], tf32-rounded
__device__ float g_BwT  [Ln*Dn];      // [l][d], tf32-rounded
__device__ float g_probs[BKKL];       // sigmoid(score)*mask, tf32-rounded
__device__ float g_part [16][BKD];    // (b? no: mode*8+split) partial contexts
__device__ float g_c    [BKD];
__device__ float g_gate [BKD];

__device__ __forceinline__ float sigmoidf(float x) {
    return 1.0f / (1.0f + __expf(-x));
}
__device__ __forceinline__ uint32_t tf32r(float x) {
    uint32_t u; asm("cvt.rna.tf32.f32 %0, %1;" : "=r"(u) : "f"(x)); return u;
}
__device__ __forceinline__ float tf32rf(float x) {
    return __uint_as_float(tf32r(x));
}
__device__ __forceinline__ void mma8(float c[4], uint32_t a0, uint32_t a1, uint32_t a2,
                                     uint32_t a3, uint32_t b0, uint32_t b1) {
    asm("mma.sync.aligned.m16n8k8.row.col.f32.tf32.tf32.f32 "
        "{%0,%1,%2,%3},{%4,%5,%6,%7},{%8,%9},{%0,%1,%2,%3};"
        : "+f"(c[0]), "+f"(c[1]), "+f"(c[2]), "+f"(c[3])
        : "r"(a0), "r"(a1), "r"(a2), "r"(a3), "r"(b0), "r"(b1));
}

// ---------------- prep: tf32-rounded weight transposes ---------------------
__global__ void prep_kernel(const float* __restrict__ out_w,
                            const float* __restrict__ A_w,
                            const float* __restrict__ B_w) {
    int i = blockIdx.x * blockDim.x + threadIdx.x;
    if (i < Hn * Ln) { int h = i / Ln, l = i - h * Ln; g_outwT[i] = tf32rf(out_w[l * Hn + h]); }
    if (i < Ln * Dn) { int l = i / Dn, d = i - l * Dn; g_AwT[i] = tf32rf(A_w[d * Ln + l]);
                                                      g_BwT[i] = tf32rf(B_w[d * Ln + l]); }
}

__global__ void copy_init_kernel(const float* __restrict__ all_vecs,
                                 const float* __restrict__ span_vecs,
                                 float* __restrict__ outAll,
                                 float* __restrict__ outU) {
    int i = blockIdx.x * blockDim.x + threadIdx.x;
    if (i < BND) outAll[i] = all_vecs[i];
    if (i < BKD) outU[i]   = span_vecs[i];
}

// ---------------- proj: [512 x 512] = u @ [left_w | right_w]^T -------------
__global__ __launch_bounds__(256) void proj_kernel(const float* __restrict__ u,
        const float* __restrict__ left_w,  const float* __restrict__ left_b,
        const float* __restrict__ right_w, const float* __restrict__ right_b) {
    __shared__ float As[128][36];
    const int tid = threadIdx.x;
    const int warp = tid >> 5, lane = tid & 31;
    const int wm = warp & 3, wn = warp >> 2;
    const int grp = lane >> 2, q = lane & 3;
    const int m0 = blockIdx.x * 128, n0 = blockIdx.y * 64;
    const bool isL = (n0 < Hn);
    const float* W    = isL ? left_w : right_w;
    const float* bias = isL ? left_b : right_b;
    float* OUT        = isL ? g_left : g_right;
    const int nloc0 = isL ? n0 : n0 - Hn;
    const int fm = tid >> 1, fh = tid & 1;
    float acc[2][4][4] = {};

    for (int kb = 0; kb < Dn; kb += 32) {
        const float* src = u + (size_t)(m0 + fm) * Dn + kb + fh * 16;
#pragma unroll
        for (int e = 0; e < 4; e++) {
            float4 v = *(const float4*)(src + 4 * e);
            int c = fh * 16 + 4 * e;
            As[fm][c + 0] = tf32rf(v.x); As[fm][c + 1] = tf32rf(v.y);
            As[fm][c + 2] = tf32rf(v.z); As[fm][c + 3] = tf32rf(v.w);
        }
        __syncthreads();
#pragma unroll
        for (int k0 = 0; k0 < 32; k0 += 8) {
            uint32_t b0[4], b1[4];
#pragma unroll
            for (int ni = 0; ni < 4; ni++) {
                int n = nloc0 + wn * 32 + ni * 8 + grp;
                b0[ni] = tf32r(W[(size_t)n * Dn + kb + k0 + q]);
                b1[ni] = tf32r(W[(size_t)n * Dn + kb + k0 + q + 4]);
            }
#pragma unroll
            for (int mi = 0; mi < 2; mi++) {
                int mb = wm * 32 + mi * 16;
                uint32_t a0 = __float_as_uint(As[mb + grp][k0 + q]);
                uint32_t a1 = __float_as_uint(As[mb + 8 + grp][k0 + q]);
                uint32_t a2 = __float_as_uint(As[mb + grp][k0 + q + 4]);
                uint32_t a3 = __float_as_uint(As[mb + 8 + grp][k0 + q + 4]);
#pragma unroll
                for (int ni = 0; ni < 4; ni++)
                    mma8(acc[mi][ni], a0, a1, a2, a3, b0[ni], b1[ni]);
            }
        }
        __syncthreads();
    }
#pragma unroll
    for (int mi = 0; mi < 2; mi++) {
        int r0 = m0 + wm * 32 + mi * 16 + grp;
#pragma unroll
        for (int ni = 0; ni < 4; ni++) {
            int c = nloc0 + wn * 32 + ni * 8 + 2 * q;
            OUT[(size_t)r0 * Hn + c]       = acc[mi][ni][0] + bias[c];
            OUT[(size_t)r0 * Hn + c + 1]   = acc[mi][ni][1] + bias[c + 1];
            OUT[(size_t)(r0 + 8) * Hn + c]     = acc[mi][ni][2] + bias[c];
            OUT[(size_t)(r0 + 8) * Hn + c + 1] = acc[mi][ni][3] + bias[c + 1];
        }
    }
}

// ---------------- fused pair-scorer + probs (64x32 warp tiles, 8 warps) ----
// block = 256 threads = 8 warps (4 m-groups x 2 n-groups)
// block tile 256j x 64l, K = h(256). grid: (1, i=256, b=2)
__global__ __launch_bounds__(256, 2) void scores_kernel(
        const int* __restrict__ span_begin, const int* __restrict__ span_end,
        const float* __restrict__ dist_emb, const float* __restrict__ out_b,
        const float* __restrict__ mask, float* __restrict__ scores) {
    __shared__ float As[256][36];
    __shared__ float Bs[32][72];
    __shared__ float leftS[Hn];
    __shared__ int   bktS[256];
    const int tid = threadIdx.x;
    const int warp = tid >> 5, lane = tid & 31;
    const int wm = warp & 3, wn = warp >> 2;
    const int grp = lane >> 2, q = lane & 3;
    const int b = blockIdx.z, i = blockIdx.y;
    const int arow = tid >> 3, aq = tid & 7;        // A-fill: 32 rows x 8 quads / pass
    const int fd4 = (tid & 15) * 4, fk2 = (tid >> 4) * 2;  // B-fill coords

    leftS[tid] = g_left[(size_t)(b * Kn + i) * Hn + tid];
    {
        int ad = abs(span_begin[b * Kn + tid] - span_end[b * Kn + i]);
        bktS[tid] = ad > 63 ? 63 : ad;
    }
    __syncthreads();

    float acc[4][4][4] = {};
    for (int hb = 0; hb < Hn; hb += 32) {
        // A tile: relu(left + right + dist), tf32
#pragma unroll
        for (int p = 0; p < 8; p++) {
            int j = p * 32 + arow;
            float4 rv = *(const float4*)&g_right[(size_t)(b * Kn + j) * Hn + hb + aq * 4];
            float4 dv = *(const float4*)&dist_emb[(size_t)bktS[j] * Hn + hb + aq * 4];
            float4 lv = *(const float4*)&leftS[hb + aq * 4];
            float4 o;
            o.x = tf32rf(fmaxf(lv.x + rv.x + dv.x, 0.f));
            o.y = tf32rf(fmaxf(lv.y + rv.y + dv.y, 0.f));
            o.z = tf32rf(fmaxf(lv.z + rv.z + dv.z, 0.f));
            o.w = tf32rf(fmaxf(lv.w + rv.w + dv.w, 0.f));
            *(float4*)&As[j][aq * 4] = o;
        }
        // B tile: out_wT chunk (already tf32)
#pragma unroll
        for (int e = 0; e < 2; e++) {
            int k = fk2 + e;
            *(float4*)&Bs[k][fd4] = *(const float4*)&g_outwT[(size_t)(hb + k) * Ln + fd4];
        }
        __syncthreads();
#pragma unroll
        for (int k0 = 0; k0 < 32; k0 += 8) {
            uint32_t b0[4], b1[4];
#pragma unroll
            for (int ni = 0; ni < 4; ni++) {
                int n = wn * 32 + ni * 8 + grp;
                b0[ni] = __float_as_uint(Bs[k0 + q][n]);
                b1[ni] = __float_as_uint(Bs[k0 + q + 4][n]);
            }
#pragma unroll
            for (int mi = 0; mi < 4; mi++) {
                int mb = wm * 64 + mi * 16;
                uint32_t a0 = __float_as_uint(As[mb + grp][k0 + q]);
                uint32_t a1 = __float_as_uint(As[mb + 8 + grp][k0 + q]);
                uint32_t a2 = __float_as_uint(As[mb + grp][k0 + q + 4]);
                uint32_t a3 = __float_as_uint(As[mb + 8 + grp][k0 + q + 4]);
#pragma unroll
                for (int ni = 0; ni < 4; ni++)
                    mma8(acc[mi][ni], a0, a1, a2, a3, b0[ni], b1[ni]);
            }
        }
        __syncthreads();
    }
    float* scRow = scores + (size_t)(b * Kn + i) * (Kn * Ln);
    float* prRow = g_probs + (size_t)(b * Kn + i) * (Kn * Ln);
    const float* mkRow = mask + (size_t)(b * Kn + i) * Kn;
#pragma unroll
    for (int mi = 0; mi < 4; mi++) {
        int j = wm * 64 + mi * 16 + grp;
        float mk0 = mkRow[j], mk1 = mkRow[j + 8];
#pragma unroll
        for (int ni = 0; ni < 4; ni++) {
            int c = wn * 32 + ni * 8 + 2 * q;
            float ob0 = out_b[c], ob1 = out_b[c + 1];
            float s00 = acc[mi][ni][0] + ob0, s01 = acc[mi][ni][1] + ob1;
            float s10 = acc[mi][ni][2] + ob0, s11 = acc[mi][ni][3] + ob1;
            *(float2*)&scRow[(size_t)j * Ln + c]       = make_float2(s00, s01);
            *(float2*)&scRow[(size_t)(j + 8) * Ln + c] = make_float2(s10, s11);
            *(float2*)&prRow[(size_t)j * Ln + c] =
                make_float2(tf32rf(sigmoidf(s00) * mk0), tf32rf(sigmoidf(s01) * mk0));
            *(float2*)&prRow[(size_t)(j + 8) * Ln + c] =
                make_float2(tf32rf(sigmoidf(s10) * mk1), tf32rf(sigmoidf(s11) * mk1));
        }
    }
}

// ---------------- context GEMMs (64x32 warp tiles, 8 warps) ----------------
// mode 0: ctxt1[b,j,d] += probs[b,i,j,l] * u[b,i,d] * AwT[l,d]   (r=(i,l))
// mode 1: ctxt2[b,i,d] += probs[b,i,j,l] * u[b,j,d] * BwT[l,d]   (r=(j,l))
// block = 256 threads, block tile 256m x 64d.
// grid: (1, d-tile=12, z = b*16 + mode*8 + split(8))
__global__ __launch_bounds__(256, 2) void ctxt_kernel(const float* __restrict__ u) {
    __shared__ float As[256][36];
    __shared__ float Bs[32][72];
    const int tid = threadIdx.x;
    const int warp = tid >> 5, lane = tid & 31;
    const int wm = warp & 3, wn = warp >> 2;
    const int grp = lane >> 2, q = lane & 3;
    const int z = blockIdx.z;
    const int b = z >> 4, mode = (z >> 3) & 1, split = z & 7;
    const int d0 = blockIdx.y * 64;
    const float* wT = (mode == 0) ? g_AwT : g_BwT;
    const float* probsB = g_probs + (size_t)b * Kn * Kn * Ln;
    const float* uB     = u       + (size_t)b * Kn * Dn;
    const int arow = tid >> 3, aq = tid & 7;
    const int fd4 = (tid & 15) * 4, fk2 = (tid >> 4) * 2;

    float acc[4][4][4] = {};
    const int rBeg = split * 2048, rEnd = rBeg + 2048;
    for (int rb = rBeg; rb < rEnd; rb += 32) {
        const int other = rb >> 6;
        const int l0 = rb & 63;
        // A tile: probs (already tf32) -> smem
#pragma unroll
        for (int p = 0; p < 8; p++) {
            int m = p * 32 + arow;
            const float* src = (mode == 0)
                ? &probsB[((size_t)other * Kn + m) * Ln + l0]
                : &probsB[((size_t)m * Kn + other) * Ln + l0];
            *(float4*)&As[m][aq * 4] = *(const float4*)(src + aq * 4);
        }
        // B tile: tf32(u[other,d] * w[l0+k][d]); w from gmem (L1-resident)
        {
            float4 uv = *(const float4*)&uB[(size_t)other * Dn + d0 + fd4];
#pragma unroll
            for (int e = 0; e < 2; e++) {
                int k = fk2 + e;
                float4 wv = *(const float4*)&wT[(size_t)(l0 + k) * Dn + d0 + fd4];
                float4 o;
                o.x = tf32rf(uv.x * wv.x); o.y = tf32rf(uv.y * wv.y);
                o.z = tf32rf(uv.z * wv.z); o.w = tf32rf(uv.w * wv.w);
                *(float4*)&Bs[k][fd4] = o;
            }
        }
        __syncthreads();
#pragma unroll
        for (int k0 = 0; k0 < 32; k0 += 8) {
            uint32_t b0[4], b1[4];
#pragma unroll
            for (int ni = 0; ni < 4; ni++) {
                int n = wn * 32 + ni * 8 + grp;
                b0[ni] = __float_as_uint(Bs[k0 + q][n]);
                b1[ni] = __float_as_uint(Bs[k0 + q + 4][n]);
            }
#pragma unroll
            for (int mi = 0; mi < 4; mi++) {
                int mb = wm * 64 + mi * 16;
                uint32_t a0 = __float_as_uint(As[mb + grp][k0 + q]);
                uint32_t a1 = __float_as_uint(As[mb + 8 + grp][k0 + q]);
                uint32_t a2 = __float_as_uint(As[mb + grp][k0 + q + 4]);
                uint32_t a3 = __float_as_uint(As[mb + 8 + grp][k0 + q + 4]);
#pragma unroll
                for (int ni = 0; ni < 4; ni++)
                    mma8(acc[mi][ni], a0, a1, a2, a3, b0[ni], b1[ni]);
            }
        }
        __syncthreads();
    }
    float* dst = g_part[mode * 8 + split];
#pragma unroll
    for (int mi = 0; mi < 4; mi++) {
        int r = wm * 64 + mi * 16 + grp;
#pragma unroll
        for (int ni = 0; ni < 4; ni++) {
            int c = d0 + wn * 32 + ni * 8 + 2 * q;
            *(float2*)&dst[((size_t)b * Kn + r) * Dn + c] =
                make_float2(acc[mi][ni][0], acc[mi][ni][1]);
            *(float2*)&dst[((size_t)b * Kn + r + 8) * Dn + c] =
                make_float2(acc[mi][ni][2], acc[mi][ni][3]);
        }
    }
}

__global__ void combine_kernel(const float* __restrict__ slen) {
    int i = blockIdx.x * blockDim.x + threadIdx.x;
    if (i < BKD) {
        int b = i / (Kn * Dn);
        float s = 0.f;
#pragma unroll
        for (int p = 0; p < 16; p++) s += g_part[p][i];
        g_c[i] = s * (1.0f / slen[b]);
    }
}

// ---------------- gate GEMM: g = sigmoid([u|c] @ gate_w^T + gate_b) --------
__global__ __launch_bounds__(256) void gate_kernel(const float* __restrict__ u,
        const float* __restrict__ gate_w, const float* __restrict__ gate_b) {
    __shared__ float As[128][36];
    const int tid = threadIdx.x;
    const int warp = tid >> 5, lane = tid & 31;
    const int wm = warp & 3, wn = warp >> 2;
    const int grp = lane >> 2, q = lane & 3;
    const int m0 = blockIdx.x * 128, n0 = blockIdx.y * 64;
    const int fm = tid >> 1, fh = tid & 1;
    float acc[2][4][4] = {};

    for (int kb = 0; kb < 2 * Dn; kb += 32) {
        const float* src = (kb < Dn)
            ? u   + (size_t)(m0 + fm) * Dn + kb + fh * 16
            : g_c + (size_t)(m0 + fm) * Dn + (kb - Dn) + fh * 16;
#pragma unroll
        for (int e = 0; e < 4; e++) {
            float4 v = *(const float4*)(src + 4 * e);
            int c = fh * 16 + 4 * e;
            As[fm][c + 0] = tf32rf(v.x); As[fm][c + 1] = tf32rf(v.y);
            As[fm][c + 2] = tf32rf(v.z); As[fm][c + 3] = tf32rf(v.w);
        }
        __syncthreads();
#pragma unroll
        for (int k0 = 0; k0 < 32; k0 += 8) {
            uint32_t b0[4], b1[4];
#pragma unroll
            for (int ni = 0; ni < 4; ni++) {
                int n = n0 + wn * 32 + ni * 8 + grp;
                b0[ni] = tf32r(gate_w[(size_t)n * (2 * Dn) + kb + k0 + q]);
                b1[ni] = tf32r(gate_w[(size_t)n * (2 * Dn) + kb + k0 + q + 4]);
            }
#pragma unroll
            for (int mi = 0; mi < 2; mi++) {
                int mb = wm * 32 + mi * 16;
                uint32_t a0 = __float_as_uint(As[mb + grp][k0 + q]);
                uint32_t a1 = __float_as_uint(As[mb + 8 + grp][k0 + q]);
                uint32_t a2 = __float_as_uint(As[mb + grp][k0 + q + 4]);
                uint32_t a3 = __float_as_uint(As[mb + 8 + grp][k0 + q + 4]);
#pragma unroll
                for (int ni = 0; ni < 4; ni++)
                    mma8(acc[mi][ni], a0, a1, a2, a3, b0[ni], b1[ni]);
            }
        }
        __syncthreads();
    }
#pragma unroll
    for (int mi = 0; mi < 2; mi++) {
        int r0 = m0 + wm * 32 + mi * 16 + grp;
#pragma unroll
        for (int ni = 0; ni < 4; ni++) {
            int c = n0 + wn * 32 + ni * 8 + 2 * q;
            g_gate[(size_t)r0 * Dn + c]         = sigmoidf(acc[mi][ni][0] + gate_b[c]);
            g_gate[(size_t)r0 * Dn + c + 1]     = sigmoidf(acc[mi][ni][1] + gate_b[c + 1]);
            g_gate[(size_t)(r0 + 8) * Dn + c]     = sigmoidf(acc[mi][ni][2] + gate_b[c]);
            g_gate[(size_t)(r0 + 8) * Dn + c + 1] = sigmoidf(acc[mi][ni][3] + gate_b[c + 1]);
        }
    }
}

__global__ void update_kernel(float* __restrict__ u) {
    int i = blockIdx.x * blockDim.x + threadIdx.x;
    if (i < BKD) {
        float g = g_gate[i];
        u[i] = g * u[i] + (1.0f - g) * g_c[i];
    }
}

__global__ void scatter_kernel(const int* __restrict__ prune, const float* __restrict__ slen,
                               const float* __restrict__ u, float* __restrict__ outAll) {
    int i = blockIdx.x * blockDim.x + threadIdx.x;
    if (i < BKD) {
        int d = i % Dn, bk = i / Dn, b = bk / Kn, k = bk % Kn;
        if ((float)k < slen[b]) {
            int row = prune[bk];
            outAll[((size_t)b * Nn + row) * Dn + d] = u[i];
        }
    }
}

// ---------------- driver ---------------------------------------------------
extern "C" void kernel_launch(void* const* d_in, const int* in_sizes, int n_in,
                              void* d_out, int out_size) {
    (void)in_sizes; (void)n_in; (void)out_size;
    const float* all_vecs  = (const float*)d_in[0];
    const float* span_vecs = (const float*)d_in[1];
    const int*   span_beg  = (const int*)  d_in[2];
    const int*   span_end  = (const int*)  d_in[3];
    const float* mask      = (const float*)d_in[4];
    const float* slen      = (const float*)d_in[5];
    const int*   prune     = (const int*)  d_in[6];
    const float* left_w    = (const float*)d_in[7];
    const float* left_b    = (const float*)d_in[8];
    const float* right_w   = (const float*)d_in[9];
    const float* right_b   = (const float*)d_in[10];
    const float* dist_emb  = (const float*)d_in[11];
    const float* out_w     = (const float*)d_in[12];
    const float* out_b     = (const float*)d_in[13];
    const float* A_w       = (const float*)d_in[14];
    const float* B_w       = (const float*)d_in[15];
    const float* gate_w    = (const float*)d_in[16];
    const float* gate_b    = (const float*)d_in[17];

    float* outAll = (float*)d_out;           // [B,N,D]
    float* outU   = outAll + BND;            // [B,K,D]
    float* outS   = outU + BKD;              // [B,K,K,L]

    prep_kernel<<<(Ln * Dn + 255) / 256, 256>>>(out_w, A_w, B_w);
    copy_init_kernel<<<(BND + 255) / 256, 256>>>(all_vecs, span_vecs, outAll, outU);

    proj_kernel<<<dim3(4, 8), 256>>>(outU, left_w, left_b, right_w, right_b);
    scores_kernel<<<dim3(1, Kn, Bn), 256>>>(span_beg, span_end, dist_emb, out_b, mask, outS);

    for (int t = 0; t < 3; t++) {
        ctxt_kernel<<<dim3(1, 12, 32), 256>>>(outU);
        combine_kernel<<<(BKD + 255) / 256, 256>>>(slen);
        gate_kernel<<<dim3(4, 12), 256>>>(outU, gate_w, gate_b);
        update_kernel<<<(BKD + 255) / 256, 256>>>(outU);
        proj_kernel<<<dim3(4, 8), 256>>>(outU, left_w, left_b, right_w, right_b);
        scores_kernel<<<dim3(1, Kn, Bn), 256>>>(span_beg, span_end, dist_emb, out_b, mask, outS);
    }

    scatter_kernel<<<(BKD + 255) / 256, 256>>>(prune, slen, outU, outAll);
}

// round 7
// speedup vs baseline: 2.7546x; 1.0662x over previous
#include <cuda_runtime.h>
#include <cstdint>

#define Bn 2
#define Nn 2048
#define Kn 256
#define Dn 768
#define Hn 256
#define Ln 64
#define BND (Bn*Nn*Dn)
#define BKD (Bn*Kn*Dn)
#define BKH (Bn*Kn*Hn)
#define BKKL ((size_t)Bn*Kn*Kn*Ln)

// ---------------- scratch (device globals; no allocations allowed) ----------
__device__ float g_left [BKH];
__device__ float g_right[BKH];
__device__ float g_outwT[Hn*Ln];      // [h][l], tf32-rounded
__device__ float g_AwT  [Ln*Dn];      // [l][d], tf32-rounded
__device__ float g_BwT  [Ln*Dn];      // [l][d], tf32-rounded
__device__ float g_probs[BKKL];       // sigmoid(score)*mask, tf32-rounded
__device__ float g_part [16][BKD];    // (mode*8+split) partial contexts
__device__ float g_c    [BKD];
__device__ float g_gate [BKD];

__device__ __forceinline__ float sigmoidf(float x) {
    return 1.0f / (1.0f + __expf(-x));
}
__device__ __forceinline__ uint32_t tf32r(float x) {
    uint32_t u; asm("cvt.rna.tf32.f32 %0, %1;" : "=r"(u) : "f"(x)); return u;
}
__device__ __forceinline__ float tf32rf(float x) {
    return __uint_as_float(tf32r(x));
}
__device__ __forceinline__ void mma8(float c[4], uint32_t a0, uint32_t a1, uint32_t a2,
                                     uint32_t a3, uint32_t b0, uint32_t b1) {
    asm("mma.sync.aligned.m16n8k8.row.col.f32.tf32.tf32.f32 "
        "{%0,%1,%2,%3},{%4,%5,%6,%7},{%8,%9},{%0,%1,%2,%3};"
        : "+f"(c[0]), "+f"(c[1]), "+f"(c[2]), "+f"(c[3])
        : "r"(a0), "r"(a1), "r"(a2), "r"(a3), "r"(b0), "r"(b1));
}
__device__ __forceinline__ void cp16(uint32_t daddr, const void* src) {
    asm volatile("cp.async.cg.shared.global [%0], [%1], 16;\n" :: "r"(daddr), "l"(src));
}

// ---------------- prep: tf32-rounded weight transposes ---------------------
__global__ void prep_kernel(const float* __restrict__ out_w,
                            const float* __restrict__ A_w,
                            const float* __restrict__ B_w) {
    int i = blockIdx.x * blockDim.x + threadIdx.x;
    if (i < Hn * Ln) { int h = i / Ln, l = i - h * Ln; g_outwT[i] = tf32rf(out_w[l * Hn + h]); }
    if (i < Ln * Dn) { int l = i / Dn, d = i - l * Dn; g_AwT[i] = tf32rf(A_w[d * Ln + l]);
                                                      g_BwT[i] = tf32rf(B_w[d * Ln + l]); }
}

__global__ void copy_init_kernel(const float* __restrict__ all_vecs,
                                 const float* __restrict__ span_vecs,
                                 float* __restrict__ outAll,
                                 float* __restrict__ outU) {
    int i = blockIdx.x * blockDim.x + threadIdx.x;
    if (i < BND) outAll[i] = all_vecs[i];
    if (i < BKD) outU[i]   = span_vecs[i];
}

// ---------------- proj: [512 x 512] = u @ [left_w | right_w]^T -------------
__global__ __launch_bounds__(256) void proj_kernel(const float* __restrict__ u,
        const float* __restrict__ left_w,  const float* __restrict__ left_b,
        const float* __restrict__ right_w, const float* __restrict__ right_b) {
    __shared__ float As[128][36];
    const int tid = threadIdx.x;
    const int warp = tid >> 5, lane = tid & 31;
    const int wm = warp & 3, wn = warp >> 2;
    const int grp = lane >> 2, q = lane & 3;
    const int m0 = blockIdx.x * 128, n0 = blockIdx.y * 64;
    const bool isL = (n0 < Hn);
    const float* W    = isL ? left_w : right_w;
    const float* bias = isL ? left_b : right_b;
    float* OUT        = isL ? g_left : g_right;
    const int nloc0 = isL ? n0 : n0 - Hn;
    const int fm = tid >> 1, fh = tid & 1;
    float acc[2][4][4] = {};

    for (int kb = 0; kb < Dn; kb += 32) {
        const float* src = u + (size_t)(m0 + fm) * Dn + kb + fh * 16;
#pragma unroll
        for (int e = 0; e < 4; e++) {
            float4 v = *(const float4*)(src + 4 * e);
            int c = fh * 16 + 4 * e;
            As[fm][c + 0] = tf32rf(v.x); As[fm][c + 1] = tf32rf(v.y);
            As[fm][c + 2] = tf32rf(v.z); As[fm][c + 3] = tf32rf(v.w);
        }
        __syncthreads();
#pragma unroll
        for (int k0 = 0; k0 < 32; k0 += 8) {
            uint32_t b0[4], b1[4];
#pragma unroll
            for (int ni = 0; ni < 4; ni++) {
                int n = nloc0 + wn * 32 + ni * 8 + grp;
                b0[ni] = tf32r(W[(size_t)n * Dn + kb + k0 + q]);
                b1[ni] = tf32r(W[(size_t)n * Dn + kb + k0 + q + 4]);
            }
#pragma unroll
            for (int mi = 0; mi < 2; mi++) {
                int mb = wm * 32 + mi * 16;
                uint32_t a0 = __float_as_uint(As[mb + grp][k0 + q]);
                uint32_t a1 = __float_as_uint(As[mb + 8 + grp][k0 + q]);
                uint32_t a2 = __float_as_uint(As[mb + grp][k0 + q + 4]);
                uint32_t a3 = __float_as_uint(As[mb + 8 + grp][k0 + q + 4]);
#pragma unroll
                for (int ni = 0; ni < 4; ni++)
                    mma8(acc[mi][ni], a0, a1, a2, a3, b0[ni], b1[ni]);
            }
        }
        __syncthreads();
    }
#pragma unroll
    for (int mi = 0; mi < 2; mi++) {
        int r0 = m0 + wm * 32 + mi * 16 + grp;
#pragma unroll
        for (int ni = 0; ni < 4; ni++) {
            int c = nloc0 + wn * 32 + ni * 8 + 2 * q;
            OUT[(size_t)r0 * Hn + c]       = acc[mi][ni][0] + bias[c];
            OUT[(size_t)r0 * Hn + c + 1]   = acc[mi][ni][1] + bias[c + 1];
            OUT[(size_t)(r0 + 8) * Hn + c]     = acc[mi][ni][2] + bias[c];
            OUT[(size_t)(r0 + 8) * Hn + c + 1] = acc[mi][ni][3] + bias[c + 1];
        }
    }
}

// ---------------- fused pair-scorer + probs (64x32 warp tiles, 8 warps) ----
// block = 256 threads = 8 warps (4 m-groups x 2 n-groups)
// block tile 256j x 64l, K = h(256). grid: (1, i=256, b=2)
__global__ __launch_bounds__(256, 2) void scores_kernel(
        const int* __restrict__ span_begin, const int* __restrict__ span_end,
        const float* __restrict__ dist_emb, const float* __restrict__ out_b,
        const float* __restrict__ mask, float* __restrict__ scores) {
    __shared__ float As[256][36];
    __shared__ float Bs[32][72];
    __shared__ float leftS[Hn];
    __shared__ int   bktS[256];
    const int tid = threadIdx.x;
    const int warp = tid >> 5, lane = tid & 31;
    const int wm = warp & 3, wn = warp >> 2;
    const int grp = lane >> 2, q = lane & 3;
    const int b = blockIdx.z, i = blockIdx.y;
    const int arow = tid >> 3, aq = tid & 7;        // A-fill: 32 rows x 8 quads / pass
    const int fd4 = (tid & 15) * 4, fk2 = (tid >> 4) * 2;  // B-fill coords

    leftS[tid] = g_left[(size_t)(b * Kn + i) * Hn + tid];
    {
        int ad = abs(span_begin[b * Kn + tid] - span_end[b * Kn + i]);
        bktS[tid] = ad > 63 ? 63 : ad;
    }
    __syncthreads();

    float acc[4][4][4] = {};
    for (int hb = 0; hb < Hn; hb += 32) {
        // A tile: relu(left + right + dist), tf32
#pragma unroll
        for (int p = 0; p < 8; p++) {
            int j = p * 32 + arow;
            float4 rv = *(const float4*)&g_right[(size_t)(b * Kn + j) * Hn + hb + aq * 4];
            float4 dv = *(const float4*)&dist_emb[(size_t)bktS[j] * Hn + hb + aq * 4];
            float4 lv = *(const float4*)&leftS[hb + aq * 4];
            float4 o;
            o.x = tf32rf(fmaxf(lv.x + rv.x + dv.x, 0.f));
            o.y = tf32rf(fmaxf(lv.y + rv.y + dv.y, 0.f));
            o.z = tf32rf(fmaxf(lv.z + rv.z + dv.z, 0.f));
            o.w = tf32rf(fmaxf(lv.w + rv.w + dv.w, 0.f));
            *(float4*)&As[j][aq * 4] = o;
        }
        // B tile: out_wT chunk (already tf32)
#pragma unroll
        for (int e = 0; e < 2; e++) {
            int k = fk2 + e;
            *(float4*)&Bs[k][fd4] = *(const float4*)&g_outwT[(size_t)(hb + k) * Ln + fd4];
        }
        __syncthreads();
#pragma unroll
        for (int k0 = 0; k0 < 32; k0 += 8) {
            uint32_t b0[4], b1[4];
#pragma unroll
            for (int ni = 0; ni < 4; ni++) {
                int n = wn * 32 + ni * 8 + grp;
                b0[ni] = __float_as_uint(Bs[k0 + q][n]);
                b1[ni] = __float_as_uint(Bs[k0 + q + 4][n]);
            }
#pragma unroll
            for (int mi = 0; mi < 4; mi++) {
                int mb = wm * 64 + mi * 16;
                uint32_t a0 = __float_as_uint(As[mb + grp][k0 + q]);
                uint32_t a1 = __float_as_uint(As[mb + 8 + grp][k0 + q]);
                uint32_t a2 = __float_as_uint(As[mb + grp][k0 + q + 4]);
                uint32_t a3 = __float_as_uint(As[mb + 8 + grp][k0 + q + 4]);
#pragma unroll
                for (int ni = 0; ni < 4; ni++)
                    mma8(acc[mi][ni], a0, a1, a2, a3, b0[ni], b1[ni]);
            }
        }
        __syncthreads();
    }
    float* scRow = scores + (size_t)(b * Kn + i) * (Kn * Ln);
    float* prRow = g_probs + (size_t)(b * Kn + i) * (Kn * Ln);
    const float* mkRow = mask + (size_t)(b * Kn + i) * Kn;
#pragma unroll
    for (int mi = 0; mi < 4; mi++) {
        int j = wm * 64 + mi * 16 + grp;
        float mk0 = mkRow[j], mk1 = mkRow[j + 8];
#pragma unroll
        for (int ni = 0; ni < 4; ni++) {
            int c = wn * 32 + ni * 8 + 2 * q;
            float ob0 = out_b[c], ob1 = out_b[c + 1];
            float s00 = acc[mi][ni][0] + ob0, s01 = acc[mi][ni][1] + ob1;
            float s10 = acc[mi][ni][2] + ob0, s11 = acc[mi][ni][3] + ob1;
            *(float2*)&scRow[(size_t)j * Ln + c]       = make_float2(s00, s01);
            *(float2*)&scRow[(size_t)(j + 8) * Ln + c] = make_float2(s10, s11);
            *(float2*)&prRow[(size_t)j * Ln + c] =
                make_float2(tf32rf(sigmoidf(s00) * mk0), tf32rf(sigmoidf(s01) * mk0));
            *(float2*)&prRow[(size_t)(j + 8) * Ln + c] =
                make_float2(tf32rf(sigmoidf(s10) * mk1), tf32rf(sigmoidf(s11) * mk1));
        }
    }
}

// ---------------- context GEMMs: cp.async double-buffered ------------------
// mode 0: ctxt1[b,j,d] += probs[b,i,j,l] * u[b,i,d] * AwT[l,d]   (r=(i,l))
// mode 1: ctxt2[b,i,d] += probs[b,i,j,l] * u[b,j,d] * BwT[l,d]   (r=(j,l))
// block = 256 threads = 8 warps (4m x 2n), block tile 256m x 64d.
// Dynamic smem: As[2][256][36] (cp.async ping-pong) + wS[64][72].
// grid: (1, d-tile=12, z = b*16 + mode*8 + split(8))
#define CTXT_SMEM ((2 * 256 * 36 + 64 * 72) * 4)
__global__ __launch_bounds__(256, 2) void ctxt_kernel(const float* __restrict__ u) {
    extern __shared__ float dsm[];
    float* AsBase = dsm;                    // 2 * 9216 floats
    float* wS     = dsm + 2 * 256 * 36;     // 64 * 72 floats (stride 72 -> frag banks 8q+grp)
    const int tid = threadIdx.x;
    const int warp = tid >> 5, lane = tid & 31;
    const int wm = warp & 3, wn = warp >> 2;
    const int grp = lane >> 2, q = lane & 3;
    const int z = blockIdx.z;
    const int b = z >> 4, mode = (z >> 3) & 1, split = z & 7;
    const int d0 = blockIdx.y * 64;
    const float* wT = (mode == 0) ? g_AwT : g_BwT;
    const float* probsB = g_probs + (size_t)b * Kn * Kn * Ln;
    const float* uB     = u       + (size_t)b * Kn * Dn;
    const int arow = tid >> 3, aq = tid & 7;

    int cn[4], dcol[4];
#pragma unroll
    for (int ni = 0; ni < 4; ni++) {
        cn[ni]   = wn * 32 + ni * 8 + grp;
        dcol[ni] = d0 + cn[ni];
    }

    // stage weight slice wS[64 l][64 d] (one-time)
    {
        int l = tid >> 2, c16 = (tid & 3) * 16;
#pragma unroll
        for (int e = 0; e < 4; e++) {
            float4 v = *(const float4*)&wT[(size_t)l * Dn + d0 + c16 + 4 * e];
            int c = c16 + 4 * e;
            wS[l * 72 + c + 0] = v.x; wS[l * 72 + c + 1] = v.y;
            wS[l * 72 + c + 2] = v.z; wS[l * 72 + c + 3] = v.w;
        }
    }

    const int rBeg = split * 2048;
    const int NC = 64;                       // 64 chunks of 32 k

    // cp.async A-tile fill for chunk c into buffer buf
    auto issueA = [&](int c, int buf) {
        int rb = rBeg + c * 32;
        int other = rb >> 6, l0 = rb & 63;
        float* dstBase = AsBase + buf * 9216;
#pragma unroll
        for (int p = 0; p < 8; p++) {
            int m = p * 32 + arow;
            const float* src = (mode == 0)
                ? &probsB[((size_t)other * Kn + m) * Ln + l0 + aq * 4]
                : &probsB[((size_t)m * Kn + other) * Ln + l0 + aq * 4];
            uint32_t daddr = (uint32_t)__cvta_generic_to_shared(dstBase + m * 36 + aq * 4);
            cp16(daddr, src);
        }
    };

    issueA(0, 0);
    asm volatile("cp.async.commit_group;\n");
    __syncthreads();   // wS visibility

    float acc[4][4][4] = {};
    float uval[4], unext[4];
    {
        int o0 = rBeg >> 6;
#pragma unroll
        for (int ni = 0; ni < 4; ni++) uval[ni] = uB[(size_t)o0 * Dn + dcol[ni]];
    }

    for (int c = 0; c < NC; c++) {
        if (c + 1 < NC) {
            issueA(c + 1, (c + 1) & 1);
            int on = (rBeg + (c + 1) * 32) >> 6;
#pragma unroll
            for (int ni = 0; ni < 4; ni++) unext[ni] = uB[(size_t)on * Dn + dcol[ni]];
        }
        asm volatile("cp.async.commit_group;\n");
        if (c + 1 < NC) asm volatile("cp.async.wait_group 1;\n");
        else            asm volatile("cp.async.wait_group 0;\n");
        __syncthreads();

        const float* AsBuf = AsBase + (c & 1) * 9216;
        const int l0 = (rBeg + c * 32) & 63;
#pragma unroll
        for (int k0 = 0; k0 < 32; k0 += 8) {
            uint32_t b0[4], b1[4];
#pragma unroll
            for (int ni = 0; ni < 4; ni++) {
                float w0 = wS[(l0 + k0 + q) * 72 + cn[ni]];
                float w1 = wS[(l0 + k0 + q + 4) * 72 + cn[ni]];
                b0[ni] = tf32r(uval[ni] * w0);
                b1[ni] = tf32r(uval[ni] * w1);
            }
#pragma unroll
            for (int mi = 0; mi < 4; mi++) {
                int mb = wm * 64 + mi * 16;
                uint32_t a0 = __float_as_uint(AsBuf[(mb + grp) * 36 + k0 + q]);
                uint32_t a1 = __float_as_uint(AsBuf[(mb + 8 + grp) * 36 + k0 + q]);
                uint32_t a2 = __float_as_uint(AsBuf[(mb + grp) * 36 + k0 + q + 4]);
                uint32_t a3 = __float_as_uint(AsBuf[(mb + 8 + grp) * 36 + k0 + q + 4]);
#pragma unroll
                for (int ni = 0; ni < 4; ni++)
                    mma8(acc[mi][ni], a0, a1, a2, a3, b0[ni], b1[ni]);
            }
        }
        __syncthreads();
#pragma unroll
        for (int ni = 0; ni < 4; ni++) uval[ni] = unext[ni];
    }

    float* dst = g_part[mode * 8 + split];
#pragma unroll
    for (int mi = 0; mi < 4; mi++) {
        int r = wm * 64 + mi * 16 + grp;
#pragma unroll
        for (int ni = 0; ni < 4; ni++) {
            int c = d0 + wn * 32 + ni * 8 + 2 * q;
            *(float2*)&dst[((size_t)b * Kn + r) * Dn + c] =
                make_float2(acc[mi][ni][0], acc[mi][ni][1]);
            *(float2*)&dst[((size_t)b * Kn + r + 8) * Dn + c] =
                make_float2(acc[mi][ni][2], acc[mi][ni][3]);
        }
    }
}

__global__ void combine_kernel(const float* __restrict__ slen) {
    int i = blockIdx.x * blockDim.x + threadIdx.x;
    if (i < BKD) {
        int b = i / (Kn * Dn);
        float s = 0.f;
#pragma unroll
        for (int p = 0; p < 16; p++) s += g_part[p][i];
        g_c[i] = s * (1.0f / slen[b]);
    }
}

// ---------------- gate GEMM: g = sigmoid([u|c] @ gate_w^T + gate_b) --------
__global__ __launch_bounds__(256) void gate_kernel(const float* __restrict__ u,
        const float* __restrict__ gate_w, const float* __restrict__ gate_b) {
    __shared__ float As[128][36];
    const int tid = threadIdx.x;
    const int warp = tid >> 5, lane = tid & 31;
    const int wm = warp & 3, wn = warp >> 2;
    const int grp = lane >> 2, q = lane & 3;
    const int m0 = blockIdx.x * 128, n0 = blockIdx.y * 64;
    const int fm = tid >> 1, fh = tid & 1;
    float acc[2][4][4] = {};

    for (int kb = 0; kb < 2 * Dn; kb += 32) {
        const float* src = (kb < Dn)
            ? u   + (size_t)(m0 + fm) * Dn + kb + fh * 16
            : g_c + (size_t)(m0 + fm) * Dn + (kb - Dn) + fh * 16;
#pragma unroll
        for (int e = 0; e < 4; e++) {
            float4 v = *(const float4*)(src + 4 * e);
            int c = fh * 16 + 4 * e;
            As[fm][c + 0] = tf32rf(v.x); As[fm][c + 1] = tf32rf(v.y);
            As[fm][c + 2] = tf32rf(v.z); As[fm][c + 3] = tf32rf(v.w);
        }
        __syncthreads();
#pragma unroll
        for (int k0 = 0; k0 < 32; k0 += 8) {
            uint32_t b0[4], b1[4];
#pragma unroll
            for (int ni = 0; ni < 4; ni++) {
                int n = n0 + wn * 32 + ni * 8 + grp;
                b0[ni] = tf32r(gate_w[(size_t)n * (2 * Dn) + kb + k0 + q]);
                b1[ni] = tf32r(gate_w[(size_t)n * (2 * Dn) + kb + k0 + q + 4]);
            }
#pragma unroll
            for (int mi = 0; mi < 2; mi++) {
                int mb = wm * 32 + mi * 16;
                uint32_t a0 = __float_as_uint(As[mb + grp][k0 + q]);
                uint32_t a1 = __float_as_uint(As[mb + 8 + grp][k0 + q]);
                uint32_t a2 = __float_as_uint(As[mb + grp][k0 + q + 4]);
                uint32_t a3 = __float_as_uint(As[mb + 8 + grp][k0 + q + 4]);
#pragma unroll
                for (int ni = 0; ni < 4; ni++)
                    mma8(acc[mi][ni], a0, a1, a2, a3, b0[ni], b1[ni]);
            }
        }
        __syncthreads();
    }
#pragma unroll
    for (int mi = 0; mi < 2; mi++) {
        int r0 = m0 + wm * 32 + mi * 16 + grp;
#pragma unroll
        for (int ni = 0; ni < 4; ni++) {
            int c = n0 + wn * 32 + ni * 8 + 2 * q;
            g_gate[(size_t)r0 * Dn + c]         = sigmoidf(acc[mi][ni][0] + gate_b[c]);
            g_gate[(size_t)r0 * Dn + c + 1]     = sigmoidf(acc[mi][ni][1] + gate_b[c + 1]);
            g_gate[(size_t)(r0 + 8) * Dn + c]     = sigmoidf(acc[mi][ni][2] + gate_b[c]);
            g_gate[(size_t)(r0 + 8) * Dn + c + 1] = sigmoidf(acc[mi][ni][3] + gate_b[c + 1]);
        }
    }
}

__global__ void update_kernel(float* __restrict__ u) {
    int i = blockIdx.x * blockDim.x + threadIdx.x;
    if (i < BKD) {
        float g = g_gate[i];
        u[i] = g * u[i] + (1.0f - g) * g_c[i];
    }
}

__global__ void scatter_kernel(const int* __restrict__ prune, const float* __restrict__ slen,
                               const float* __restrict__ u, float* __restrict__ outAll) {
    int i = blockIdx.x * blockDim.x + threadIdx.x;
    if (i < BKD) {
        int d = i % Dn, bk = i / Dn, b = bk / Kn, k = bk % Kn;
        if ((float)k < slen[b]) {
            int row = prune[bk];
            outAll[((size_t)b * Nn + row) * Dn + d] = u[i];
        }
    }
}

// ---------------- driver ---------------------------------------------------
extern "C" void kernel_launch(void* const* d_in, const int* in_sizes, int n_in,
                              void* d_out, int out_size) {
    (void)in_sizes; (void)n_in; (void)out_size;
    const float* all_vecs  = (const float*)d_in[0];
    const float* span_vecs = (const float*)d_in[1];
    const int*   span_beg  = (const int*)  d_in[2];
    const int*   span_end  = (const int*)  d_in[3];
    const float* mask      = (const float*)d_in[4];
    const float* slen      = (const float*)d_in[5];
    const int*   prune     = (const int*)  d_in[6];
    const float* left_w    = (const float*)d_in[7];
    const float* left_b    = (const float*)d_in[8];
    const float* right_w   = (const float*)d_in[9];
    const float* right_b   = (const float*)d_in[10];
    const float* dist_emb  = (const float*)d_in[11];
    const float* out_w     = (const float*)d_in[12];
    const float* out_b     = (const float*)d_in[13];
    const float* A_w       = (const float*)d_in[14];
    const float* B_w       = (const float*)d_in[15];
    const float* gate_w    = (const float*)d_in[16];
    const float* gate_b    = (const float*)d_in[17];

    float* outAll = (float*)d_out;           // [B,N,D]
    float* outU   = outAll + BND;            // [B,K,D]
    float* outS   = outU + BKD;              // [B,K,K,L]

    static int attr_done = 0;
    if (!attr_done) {
        cudaFuncSetAttribute(ctxt_kernel,
                             cudaFuncAttributeMaxDynamicSharedMemorySize, CTXT_SMEM);
        attr_done = 1;
    }

    prep_kernel<<<(Ln * Dn + 255) / 256, 256>>>(out_w, A_w, B_w);
    copy_init_kernel<<<(BND + 255) / 256, 256>>>(all_vecs, span_vecs, outAll, outU);

    proj_kernel<<<dim3(4, 8), 256>>>(outU, left_w, left_b, right_w, right_b);
    scores_kernel<<<dim3(1, Kn, Bn), 256>>>(span_beg, span_end, dist_emb, out_b, mask, outS);

    for (int t = 0; t < 3; t++) {
        ctxt_kernel<<<dim3(1, 12, 32), 256, CTXT_SMEM>>>(outU);
        combine_kernel<<<(BKD + 255) / 256, 256>>>(slen);
        gate_kernel<<<dim3(4, 12), 256>>>(outU, gate_w, gate_b);
        update_kernel<<<(BKD + 255) / 256, 256>>>(outU);
        proj_kernel<<<dim3(4, 8), 256>>>(outU, left_w, left_b, right_w, right_b);
        scores_kernel<<<dim3(1, Kn, Bn), 256>>>(span_beg, span_end, dist_emb, out_b, mask, outS);
    }

    scatter_kernel<<<(BKD + 255) / 256, 256>>>(prune, slen, outU, outAll);
}

// round 8
// speedup vs baseline: 3.6537x; 1.3264x over previous
#include <cuda_runtime.h>
#include <cstdint>

#define Bn 2
#define Nn 2048
#define Kn 256
#define Dn 768
#define Hn 256
#define Ln 64
#define BND (Bn*Nn*Dn)
#define BKD (Bn*Kn*Dn)
#define BKH (Bn*Kn*Hn)
#define BKKL ((size_t)Bn*Kn*Kn*Ln)

// ---------------- scratch (device globals; no allocations allowed) ----------
__device__ float g_left [BKH];
__device__ float g_right[BKH];
__device__ float g_outwT[Hn*Ln];      // [h][l], tf32-rounded
__device__ float g_AwT  [Ln*Dn];      // [l][d], tf32-rounded
__device__ float g_BwT  [Ln*Dn];      // [l][d], tf32-rounded
__device__ float g_probs[BKKL];       // sigmoid(score)*mask, tf32-rounded
__device__ float g_part [16][BKD];    // ctxt partials; slots 0..2 reused by proj, 3..6 by gate
__device__ float g_c    [BKD];
__device__ float g_gate [BKD];

__device__ __forceinline__ float sigmoidf(float x) {
    return 1.0f / (1.0f + __expf(-x));
}
__device__ __forceinline__ uint32_t tf32r(float x) {
    uint32_t u; asm("cvt.rna.tf32.f32 %0, %1;" : "=r"(u) : "f"(x)); return u;
}
__device__ __forceinline__ float tf32rf(float x) {
    return __uint_as_float(tf32r(x));
}
__device__ __forceinline__ void mma8(float c[4], uint32_t a0, uint32_t a1, uint32_t a2,
                                     uint32_t a3, uint32_t b0, uint32_t b1) {
    asm("mma.sync.aligned.m16n8k8.row.col.f32.tf32.tf32.f32 "
        "{%0,%1,%2,%3},{%4,%5,%6,%7},{%8,%9},{%0,%1,%2,%3};"
        : "+f"(c[0]), "+f"(c[1]), "+f"(c[2]), "+f"(c[3])
        : "r"(a0), "r"(a1), "r"(a2), "r"(a3), "r"(b0), "r"(b1));
}
__device__ __forceinline__ void cp16(uint32_t daddr, const void* src) {
    asm volatile("cp.async.cg.shared.global [%0], [%1], 16;\n" :: "r"(daddr), "l"(src));
}

// ---------------- prep: tf32-rounded weight transposes ---------------------
__global__ void prep_kernel(const float* __restrict__ out_w,
                            const float* __restrict__ A_w,
                            const float* __restrict__ B_w) {
    int i = blockIdx.x * blockDim.x + threadIdx.x;
    if (i < Hn * Ln) { int h = i / Ln, l = i - h * Ln; g_outwT[i] = tf32rf(out_w[l * Hn + h]); }
    if (i < Ln * Dn) { int l = i / Dn, d = i - l * Dn; g_AwT[i] = tf32rf(A_w[d * Ln + l]);
                                                      g_BwT[i] = tf32rf(B_w[d * Ln + l]); }
}

__global__ void copy_init_kernel(const float* __restrict__ all_vecs,
                                 const float* __restrict__ span_vecs,
                                 float* __restrict__ outAll,
                                 float* __restrict__ outU) {
    int i = blockIdx.x * blockDim.x + threadIdx.x;
    if (i < BND) outAll[i] = all_vecs[i];
    if (i < BKD) outU[i]   = span_vecs[i];
}

// ---------------- proj split-K: partials for u @ [left_w|right_w]^T --------
// grid (4, 8, 3): m-tile 128, n-tile 64 over 512 cols, split z covers k [z*256,(z+1)*256)
// partial -> g_part[z][m * 512 + n]
__global__ __launch_bounds__(256) void proj_kernel(const float* __restrict__ u,
        const float* __restrict__ left_w, const float* __restrict__ right_w) {
    __shared__ float As[128][36];
    const int tid = threadIdx.x;
    const int warp = tid >> 5, lane = tid & 31;
    const int wm = warp & 3, wn = warp >> 2;
    const int grp = lane >> 2, q = lane & 3;
    const int m0 = blockIdx.x * 128, n0 = blockIdx.y * 64;
    const int kBeg = blockIdx.z * 256, kEnd = kBeg + 256;
    const bool isL = (n0 < Hn);
    const float* W = isL ? left_w : right_w;
    const int nloc0 = isL ? n0 : n0 - Hn;
    const int fm = tid >> 1, fh = tid & 1;
    float acc[2][4][4] = {};

    for (int kb = kBeg; kb < kEnd; kb += 32) {
        const float* src = u + (size_t)(m0 + fm) * Dn + kb + fh * 16;
#pragma unroll
        for (int e = 0; e < 4; e++) {
            float4 v = *(const float4*)(src + 4 * e);
            int c = fh * 16 + 4 * e;
            As[fm][c + 0] = tf32rf(v.x); As[fm][c + 1] = tf32rf(v.y);
            As[fm][c + 2] = tf32rf(v.z); As[fm][c + 3] = tf32rf(v.w);
        }
        __syncthreads();
#pragma unroll
        for (int k0 = 0; k0 < 32; k0 += 8) {
            uint32_t b0[4], b1[4];
#pragma unroll
            for (int ni = 0; ni < 4; ni++) {
                int n = nloc0 + wn * 32 + ni * 8 + grp;
                b0[ni] = tf32r(W[(size_t)n * Dn + kb + k0 + q]);
                b1[ni] = tf32r(W[(size_t)n * Dn + kb + k0 + q + 4]);
            }
#pragma unroll
            for (int mi = 0; mi < 2; mi++) {
                int mb = wm * 32 + mi * 16;
                uint32_t a0 = __float_as_uint(As[mb + grp][k0 + q]);
                uint32_t a1 = __float_as_uint(As[mb + 8 + grp][k0 + q]);
                uint32_t a2 = __float_as_uint(As[mb + grp][k0 + q + 4]);
                uint32_t a3 = __float_as_uint(As[mb + 8 + grp][k0 + q + 4]);
#pragma unroll
                for (int ni = 0; ni < 4; ni++)
                    mma8(acc[mi][ni], a0, a1, a2, a3, b0[ni], b1[ni]);
            }
        }
        __syncthreads();
    }
    float* dst = g_part[blockIdx.z];
#pragma unroll
    for (int mi = 0; mi < 2; mi++) {
        int r0 = m0 + wm * 32 + mi * 16 + grp;
#pragma unroll
        for (int ni = 0; ni < 4; ni++) {
            int c = n0 + wn * 32 + ni * 8 + 2 * q;
            dst[(size_t)r0 * 512 + c]           = acc[mi][ni][0];
            dst[(size_t)r0 * 512 + c + 1]       = acc[mi][ni][1];
            dst[(size_t)(r0 + 8) * 512 + c]     = acc[mi][ni][2];
            dst[(size_t)(r0 + 8) * 512 + c + 1] = acc[mi][ni][3];
        }
    }
}

__global__ void combine_proj_kernel(const float* __restrict__ left_b,
                                    const float* __restrict__ right_b) {
    int i = blockIdx.x * blockDim.x + threadIdx.x;   // 512*512
    if (i < 512 * 512) {
        int m = i >> 9, n = i & 511;
        float s = g_part[0][i] + g_part[1][i] + g_part[2][i];
        if (n < Hn) g_left [(size_t)m * Hn + n]      = s + left_b[n];
        else        g_right[(size_t)m * Hn + n - Hn] = s + right_b[n - Hn];
    }
}

// ---------------- fused pair-scorer + probs (R3 config: 32x32 warp tiles) --
// block = 256 threads = 8 warps (4 m x 2 n), block tile 128j x 64l, K=h(256)
// grid: (2, i=256, b=2)
__global__ __launch_bounds__(256) void scores_kernel(
        const int* __restrict__ span_begin, const int* __restrict__ span_end,
        const float* __restrict__ dist_emb, const float* __restrict__ out_b,
        const float* __restrict__ mask, float* __restrict__ scores) {
    __shared__ float As[128][36];
    __shared__ float oS[32][72];
    __shared__ float leftS[Hn];
    const int tid = threadIdx.x;
    const int warp = tid >> 5, lane = tid & 31;
    const int wm = warp & 3, wn = warp >> 2;
    const int grp = lane >> 2, q = lane & 3;
    const int b = blockIdx.z, i = blockIdx.y, j0 = blockIdx.x * 128;
    const int fm = tid >> 1, fh = tid & 1;
    const int fn = tid & 63, fk = tid >> 6;

    leftS[tid] = g_left[(size_t)(b * Kn + i) * Hn + tid];
    int dd = span_begin[b * Kn + j0 + fm] - span_end[b * Kn + i];
    int ad = abs(dd); const int bkt = ad > 63 ? 63 : ad;
    __syncthreads();

    float acc[2][4][4] = {};
    for (int hb = 0; hb < Hn; hb += 32) {
        const float* rsrc = g_right + (size_t)(b * Kn + j0 + fm) * Hn + hb + fh * 16;
        const float* dsrc = dist_emb + (size_t)bkt * Hn + hb + fh * 16;
#pragma unroll
        for (int e = 0; e < 4; e++) {
            float4 rv = *(const float4*)(rsrc + 4 * e);
            float4 dv = *(const float4*)(dsrc + 4 * e);
            int c = fh * 16 + 4 * e;
            float4 lv = *(const float4*)(&leftS[hb + c]);
            As[fm][c + 0] = tf32rf(fmaxf(lv.x + rv.x + dv.x, 0.f));
            As[fm][c + 1] = tf32rf(fmaxf(lv.y + rv.y + dv.y, 0.f));
            As[fm][c + 2] = tf32rf(fmaxf(lv.z + rv.z + dv.z, 0.f));
            As[fm][c + 3] = tf32rf(fmaxf(lv.w + rv.w + dv.w, 0.f));
        }
#pragma unroll
        for (int e = 0; e < 8; e++)
            oS[fk * 8 + e][fn] = g_outwT[(size_t)(hb + fk * 8 + e) * Ln + fn];
        __syncthreads();
#pragma unroll
        for (int k0 = 0; k0 < 32; k0 += 8) {
            uint32_t b0[4], b1[4];
#pragma unroll
            for (int ni = 0; ni < 4; ni++) {
                int n = wn * 32 + ni * 8 + grp;
                b0[ni] = __float_as_uint(oS[k0 + q][n]);
                b1[ni] = __float_as_uint(oS[k0 + q + 4][n]);
            }
#pragma unroll
            for (int mi = 0; mi < 2; mi++) {
                int mb = wm * 32 + mi * 16;
                uint32_t a0 = __float_as_uint(As[mb + grp][k0 + q]);
                uint32_t a1 = __float_as_uint(As[mb + 8 + grp][k0 + q]);
                uint32_t a2 = __float_as_uint(As[mb + grp][k0 + q + 4]);
                uint32_t a3 = __float_as_uint(As[mb + 8 + grp][k0 + q + 4]);
#pragma unroll
                for (int ni = 0; ni < 4; ni++)
                    mma8(acc[mi][ni], a0, a1, a2, a3, b0[ni], b1[ni]);
            }
        }
        __syncthreads();
    }
    float* scRow = scores + (size_t)(b * Kn + i) * (Kn * Ln);
    float* prRow = g_probs + (size_t)(b * Kn + i) * (Kn * Ln);
    const float* mkRow = mask + (size_t)(b * Kn + i) * Kn;
#pragma unroll
    for (int mi = 0; mi < 2; mi++) {
        int j0l = wm * 32 + mi * 16 + grp;
        float mk0 = mkRow[j0 + j0l], mk1 = mkRow[j0 + j0l + 8];
#pragma unroll
        for (int ni = 0; ni < 4; ni++) {
            int c = wn * 32 + ni * 8 + 2 * q;
#pragma unroll
            for (int e = 0; e < 2; e++) {
                float s0 = acc[mi][ni][e]     + out_b[c + e];
                float s1 = acc[mi][ni][2 + e] + out_b[c + e];
                scRow[(size_t)(j0 + j0l) * Ln + c + e]     = s0;
                scRow[(size_t)(j0 + j0l + 8) * Ln + c + e] = s1;
                prRow[(size_t)(j0 + j0l) * Ln + c + e]     = tf32rf(sigmoidf(s0) * mk0);
                prRow[(size_t)(j0 + j0l + 8) * Ln + c + e] = tf32rf(sigmoidf(s1) * mk1);
            }
        }
    }
}

// ---------------- context GEMMs: cp.async double-buffered ------------------
// block = 256 threads = 8 warps (4m x 2n), block tile 256m x 64d.
// grid: (1, d-tile=12, z = b*16 + mode*8 + split(8))
#define CTXT_SMEM ((2 * 256 * 36 + 64 * 72) * 4)
__global__ __launch_bounds__(256, 2) void ctxt_kernel(const float* __restrict__ u) {
    extern __shared__ float dsm[];
    float* AsBase = dsm;
    float* wS     = dsm + 2 * 256 * 36;
    const int tid = threadIdx.x;
    const int warp = tid >> 5, lane = tid & 31;
    const int wm = warp & 3, wn = warp >> 2;
    const int grp = lane >> 2, q = lane & 3;
    const int z = blockIdx.z;
    const int b = z >> 4, mode = (z >> 3) & 1, split = z & 7;
    const int d0 = blockIdx.y * 64;
    const float* wT = (mode == 0) ? g_AwT : g_BwT;
    const float* probsB = g_probs + (size_t)b * Kn * Kn * Ln;
    const float* uB     = u       + (size_t)b * Kn * Dn;
    const int arow = tid >> 3, aq = tid & 7;

    int cn[4], dcol[4];
#pragma unroll
    for (int ni = 0; ni < 4; ni++) {
        cn[ni]   = wn * 32 + ni * 8 + grp;
        dcol[ni] = d0 + cn[ni];
    }

    {
        int l = tid >> 2, c16 = (tid & 3) * 16;
#pragma unroll
        for (int e = 0; e < 4; e++) {
            float4 v = *(const float4*)&wT[(size_t)l * Dn + d0 + c16 + 4 * e];
            int c = c16 + 4 * e;
            wS[l * 72 + c + 0] = v.x; wS[l * 72 + c + 1] = v.y;
            wS[l * 72 + c + 2] = v.z; wS[l * 72 + c + 3] = v.w;
        }
    }

    const int rBeg = split * 2048;
    const int NC = 64;

    auto issueA = [&](int c, int buf) {
        int rb = rBeg + c * 32;
        int other = rb >> 6, l0 = rb & 63;
        float* dstBase = AsBase + buf * 9216;
#pragma unroll
        for (int p = 0; p < 8; p++) {
            int m = p * 32 + arow;
            const float* src = (mode == 0)
                ? &probsB[((size_t)other * Kn + m) * Ln + l0 + aq * 4]
                : &probsB[((size_t)m * Kn + other) * Ln + l0 + aq * 4];
            uint32_t daddr = (uint32_t)__cvta_generic_to_shared(dstBase + m * 36 + aq * 4);
            cp16(daddr, src);
        }
    };

    issueA(0, 0);
    asm volatile("cp.async.commit_group;\n");
    __syncthreads();

    float acc[4][4][4] = {};
    float uval[4], unext[4];
    {
        int o0 = rBeg >> 6;
#pragma unroll
        for (int ni = 0; ni < 4; ni++) uval[ni] = uB[(size_t)o0 * Dn + dcol[ni]];
    }

    for (int c = 0; c < NC; c++) {
        if (c + 1 < NC) {
            issueA(c + 1, (c + 1) & 1);
            int on = (rBeg + (c + 1) * 32) >> 6;
#pragma unroll
            for (int ni = 0; ni < 4; ni++) unext[ni] = uB[(size_t)on * Dn + dcol[ni]];
        }
        asm volatile("cp.async.commit_group;\n");
        if (c + 1 < NC) asm volatile("cp.async.wait_group 1;\n");
        else            asm volatile("cp.async.wait_group 0;\n");
        __syncthreads();

        const float* AsBuf = AsBase + (c & 1) * 9216;
        const int l0 = (rBeg + c * 32) & 63;
#pragma unroll
        for (int k0 = 0; k0 < 32; k0 += 8) {
            uint32_t b0[4], b1[4];
#pragma unroll
            for (int ni = 0; ni < 4; ni++) {
                float w0 = wS[(l0 + k0 + q) * 72 + cn[ni]];
                float w1 = wS[(l0 + k0 + q + 4) * 72 + cn[ni]];
                b0[ni] = __float_as_uint(uval[ni] * w0);   // mma reads tf32 bits (RZ)
                b1[ni] = __float_as_uint(uval[ni] * w1);
            }
#pragma unroll
            for (int mi = 0; mi < 4; mi++) {
                int mb = wm * 64 + mi * 16;
                uint32_t a0 = __float_as_uint(AsBuf[(mb + grp) * 36 + k0 + q]);
                uint32_t a1 = __float_as_uint(AsBuf[(mb + 8 + grp) * 36 + k0 + q]);
                uint32_t a2 = __float_as_uint(AsBuf[(mb + grp) * 36 + k0 + q + 4]);
                uint32_t a3 = __float_as_uint(AsBuf[(mb + 8 + grp) * 36 + k0 + q + 4]);
#pragma unroll
                for (int ni = 0; ni < 4; ni++)
                    mma8(acc[mi][ni], a0, a1, a2, a3, b0[ni], b1[ni]);
            }
        }
        __syncthreads();
#pragma unroll
        for (int ni = 0; ni < 4; ni++) uval[ni] = unext[ni];
    }

    float* dst = g_part[mode * 8 + split];
#pragma unroll
    for (int mi = 0; mi < 4; mi++) {
        int r = wm * 64 + mi * 16 + grp;
#pragma unroll
        for (int ni = 0; ni < 4; ni++) {
            int c = d0 + wn * 32 + ni * 8 + 2 * q;
            *(float2*)&dst[((size_t)b * Kn + r) * Dn + c] =
                make_float2(acc[mi][ni][0], acc[mi][ni][1]);
            *(float2*)&dst[((size_t)b * Kn + r + 8) * Dn + c] =
                make_float2(acc[mi][ni][2], acc[mi][ni][3]);
        }
    }
}

__global__ void combine_kernel(const float* __restrict__ slen) {
    int i = blockIdx.x * blockDim.x + threadIdx.x;
    if (i < BKD) {
        int b = i / (Kn * Dn);
        float s = 0.f;
#pragma unroll
        for (int p = 0; p < 16; p++) s += g_part[p][i];
        g_c[i] = s * (1.0f / slen[b]);
    }
}

// ---------------- gate split-K: partials of [u|c] @ gate_w^T ---------------
// grid (4, 12, 4): split z covers k [z*384,(z+1)*384); z<2 -> u, z>=2 -> g_c
// partial -> g_part[3+z][m * 768 + n]
__global__ __launch_bounds__(256) void gate_kernel(const float* __restrict__ u,
        const float* __restrict__ gate_w) {
    __shared__ float As[128][36];
    const int tid = threadIdx.x;
    const int warp = tid >> 5, lane = tid & 31;
    const int wm = warp & 3, wn = warp >> 2;
    const int grp = lane >> 2, q = lane & 3;
    const int m0 = blockIdx.x * 128, n0 = blockIdx.y * 64;
    const int kBeg = blockIdx.z * 384, kEnd = kBeg + 384;
    const int fm = tid >> 1, fh = tid & 1;
    float acc[2][4][4] = {};

    for (int kb = kBeg; kb < kEnd; kb += 32) {
        const float* src = (kb < Dn)
            ? u   + (size_t)(m0 + fm) * Dn + kb + fh * 16
            : g_c + (size_t)(m0 + fm) * Dn + (kb - Dn) + fh * 16;
#pragma unroll
        for (int e = 0; e < 4; e++) {
            float4 v = *(const float4*)(src + 4 * e);
            int c = fh * 16 + 4 * e;
            As[fm][c + 0] = tf32rf(v.x); As[fm][c + 1] = tf32rf(v.y);
            As[fm][c + 2] = tf32rf(v.z); As[fm][c + 3] = tf32rf(v.w);
        }
        __syncthreads();
#pragma unroll
        for (int k0 = 0; k0 < 32; k0 += 8) {
            uint32_t b0[4], b1[4];
#pragma unroll
            for (int ni = 0; ni < 4; ni++) {
                int n = n0 + wn * 32 + ni * 8 + grp;
                b0[ni] = tf32r(gate_w[(size_t)n * (2 * Dn) + kb + k0 + q]);
                b1[ni] = tf32r(gate_w[(size_t)n * (2 * Dn) + kb + k0 + q + 4]);
            }
#pragma unroll
            for (int mi = 0; mi < 2; mi++) {
                int mb = wm * 32 + mi * 16;
                uint32_t a0 = __float_as_uint(As[mb + grp][k0 + q]);
                uint32_t a1 = __float_as_uint(As[mb + 8 + grp][k0 + q]);
                uint32_t a2 = __float_as_uint(As[mb + grp][k0 + q + 4]);
                uint32_t a3 = __float_as_uint(As[mb + 8 + grp][k0 + q + 4]);
#pragma unroll
                for (int ni = 0; ni < 4; ni++)
                    mma8(acc[mi][ni], a0, a1, a2, a3, b0[ni], b1[ni]);
            }
        }
        __syncthreads();
    }
    float* dst = g_part[3 + blockIdx.z];
#pragma unroll
    for (int mi = 0; mi < 2; mi++) {
        int r0 = m0 + wm * 32 + mi * 16 + grp;
#pragma unroll
        for (int ni = 0; ni < 4; ni++) {
            int c = n0 + wn * 32 + ni * 8 + 2 * q;
            dst[(size_t)r0 * Dn + c]           = acc[mi][ni][0];
            dst[(size_t)r0 * Dn + c + 1]       = acc[mi][ni][1];
            dst[(size_t)(r0 + 8) * Dn + c]     = acc[mi][ni][2];
            dst[(size_t)(r0 + 8) * Dn + c + 1] = acc[mi][ni][3];
        }
    }
}

__global__ void combine_gate_update_kernel(const float* __restrict__ gate_b,
                                           float* __restrict__ u) {
    int i = blockIdx.x * blockDim.x + threadIdx.x;
    if (i < BKD) {
        int n = i % Dn;
        float s = g_part[3][i] + g_part[4][i] + g_part[5][i] + g_part[6][i];
        float g = sigmoidf(s + gate_b[n]);
        u[i] = g * u[i] + (1.0f - g) * g_c[i];
    }
}

__global__ void scatter_kernel(const int* __restrict__ prune, const float* __restrict__ slen,
                               const float* __restrict__ u, float* __restrict__ outAll) {
    int i = blockIdx.x * blockDim.x + threadIdx.x;
    if (i < BKD) {
        int d = i % Dn, bk = i / Dn, b = bk / Kn, k = bk % Kn;
        if ((float)k < slen[b]) {
            int row = prune[bk];
            outAll[((size_t)b * Nn + row) * Dn + d] = u[i];
        }
    }
}

// ---------------- driver ---------------------------------------------------
extern "C" void kernel_launch(void* const* d_in, const int* in_sizes, int n_in,
                              void* d_out, int out_size) {
    (void)in_sizes; (void)n_in; (void)out_size;
    const float* all_vecs  = (const float*)d_in[0];
    const float* span_vecs = (const float*)d_in[1];
    const int*   span_beg  = (const int*)  d_in[2];
    const int*   span_end  = (const int*)  d_in[3];
    const float* mask      = (const float*)d_in[4];
    const float* slen      = (const float*)d_in[5];
    const int*   prune     = (const int*)  d_in[6];
    const float* left_w    = (const float*)d_in[7];
    const float* left_b    = (const float*)d_in[8];
    const float* right_w   = (const float*)d_in[9];
    const float* right_b   = (const float*)d_in[10];
    const float* dist_emb  = (const float*)d_in[11];
    const float* out_w     = (const float*)d_in[12];
    const float* out_b     = (const float*)d_in[13];
    const float* A_w       = (const float*)d_in[14];
    const float* B_w       = (const float*)d_in[15];
    const float* gate_w    = (const float*)d_in[16];
    const float* gate_b    = (const float*)d_in[17];

    float* outAll = (float*)d_out;           // [B,N,D]
    float* outU   = outAll + BND;            // [B,K,D]
    float* outS   = outU + BKD;              // [B,K,K,L]

    static int attr_done = 0;
    if (!attr_done) {
        cudaFuncSetAttribute(ctxt_kernel,
                             cudaFuncAttributeMaxDynamicSharedMemorySize, CTXT_SMEM);
        attr_done = 1;
    }

    prep_kernel<<<(Ln * Dn + 255) / 256, 256>>>(out_w, A_w, B_w);
    copy_init_kernel<<<(BND + 255) / 256, 256>>>(all_vecs, span_vecs, outAll, outU);

    proj_kernel<<<dim3(4, 8, 3), 256>>>(outU, left_w, right_w);
    combine_proj_kernel<<<(512 * 512 + 255) / 256, 256>>>(left_b, right_b);
    scores_kernel<<<dim3(2, Kn, Bn), 256>>>(span_beg, span_end, dist_emb, out_b, mask, outS);

    for (int t = 0; t < 3; t++) {
        ctxt_kernel<<<dim3(1, 12, 32), 256, CTXT_SMEM>>>(outU);
        combine_kernel<<<(BKD + 255) / 256, 256>>>(slen);
        gate_kernel<<<dim3(4, 12, 4), 256>>>(outU, gate_w);
        combine_gate_update_kernel<<<(BKD + 255) / 256, 256>>>(gate_b, outU);
        proj_kernel<<<dim3(4, 8, 3), 256>>>(outU, left_w, right_w);
        combine_proj_kernel<<<(512 * 512 + 255) / 256, 256>>>(left_b, right_b);
        scores_kernel<<<dim3(2, Kn, Bn), 256>>>(span_beg, span_end, dist_emb, out_b, mask, outS);
    }

    scatter_kernel<<<(BKD + 255) / 256, 256>>>(prune, slen, outU, outAll);
}